// round 1
// baseline (speedup 1.0000x reference)
#include <cuda_runtime.h>
#include <cuda_bf16.h>
#include <math.h>

// Problem constants
#define BATCH 128
#define CIN   256
#define HCH   256   // hidden / output channels (all stages 256)

// Scratch (static __device__ allocations are the allowed scratch mechanism)
__device__ float g_kbuf[BATCH * HCH * 5 * 5];        // kernel tower out  [B,256,5,5]
__device__ float g_sbuf[BATCH * HCH * 29 * 29];      // search tower out  [B,256,29,29]
__device__ float g_feat[BATCH * HCH * 25 * 25];      // xcorr out         [B,256,25,25]
__device__ float g_hbuf[BATCH * HCH * 25 * 25];      // head1 out
__device__ float g_wkT[2304 * HCH];                  // folded+transposed weights [K][OC]
__device__ float g_wsT[2304 * HCH];
__device__ float g_wh1T[256 * HCH];
__device__ float g_wh2T[256 * HCH];
__device__ float g_biask[HCH];
__device__ float g_biass[HCH];
__device__ float g_biash[HCH];

// ---------------------------------------------------------------------------
// Fold BN into weights and transpose to [K][OC] for coalesced B-tile loads.
//   wT[k*256+oc] = w[oc*K+k] * inv(oc);  bias[oc] = beta - mean*inv
// ---------------------------------------------------------------------------
__global__ void fold_weights_bn(const float* __restrict__ w,
                                const float* __restrict__ gamma,
                                const float* __restrict__ beta,
                                const float* __restrict__ mean,
                                const float* __restrict__ var,
                                float* __restrict__ wT,
                                float* __restrict__ biasOut, int K)
{
    int idx = blockIdx.x * blockDim.x + threadIdx.x;
    if (idx >= K * HCH) return;
    int k = idx / HCH, oc = idx % HCH;
    float inv = rsqrtf(var[oc] + 1e-5f) * gamma[oc];
    wT[idx] = w[(size_t)oc * K + k] * inv;
    if (k == 0) biasOut[oc] = beta[oc] - mean[oc] * inv;
}

__global__ void transpose_w(const float* __restrict__ w, float* __restrict__ wT, int K)
{
    int idx = blockIdx.x * blockDim.x + threadIdx.x;
    if (idx >= K * HCH) return;
    int k = idx / HCH, oc = idx % HCH;
    wT[idx] = w[(size_t)oc * K + k];
}

// ---------------------------------------------------------------------------
// Implicit-GEMM conv (stride 1, VALID). One batch per blockIdx.z.
// A[p,k] = in[b, ic, y+u, x+v] with k = ic*KS*KS + u*KS + v (im2col on the fly)
// B[k,oc] = wT (pre-folded). C[p,oc] -> out[b,oc,p], +bias, optional ReLU.
// Block tile: BM x 64, K-chunk 8, thread tile TM x 4, 256 threads.
// ---------------------------------------------------------------------------
template<int KS, int BM, int TM, bool RELU>
__global__ void conv_gemm(const float* __restrict__ in,
                          const float* __restrict__ wT,
                          const float* __restrict__ bias,
                          float* __restrict__ out,
                          int Hin, int Win, int Hout, int Wout)
{
    constexpr int BN = 64, BK = 8, TN = 4;
    constexpr int KK = KS * KS;
    const int M = Hout * Wout;
    const int K = CIN * KK;
    const int b  = blockIdx.z;
    const int m0 = blockIdx.x * BM;
    const int n0 = blockIdx.y * BN;
    const int tid = threadIdx.x;

    __shared__ float As[BK][BM];
    __shared__ float Bs[BK][BN];

    const float* inb = in + (size_t)b * CIN * Hin * Win;

    float acc[TM][TN];
#pragma unroll
    for (int i = 0; i < TM; i++)
#pragma unroll
        for (int j = 0; j < TN; j++) acc[i][j] = 0.f;

    const int ty = tid / 16;       // pixel group (0..15)
    const int tx = tid % 16;       // oc group (0..15)

    // A-load mapping
    const int ap  = tid % BM;                 // pixel within tile
    const int ak0 = tid / BM;                 // starting k row
    constexpr int AK_STEP = 256 / BM;         // 4 for BM=64, 8 for BM=32
    const int p = m0 + ap;
    const bool pvalid = (p < M);
    const int py = pvalid ? p / Wout : 0;
    const int px = pvalid ? p % Wout : 0;

    // B-load mapping
    const int bo  = tid % BN;
    const int bk0 = tid / BN;                 // 0..3

    for (int k0 = 0; k0 < K; k0 += BK) {
        // ---- load A tile (im2col gather) ----
#pragma unroll
        for (int kk = ak0; kk < BK; kk += AK_STEP) {
            int k = k0 + kk;
            float v = 0.f;
            if (pvalid) {
                int ic = k / KK;
                int t  = k - ic * KK;
                int u  = t / KS;
                int vv = t - u * KS;
                v = inb[ic * Hin * Win + (py + u) * Win + (px + vv)];
            }
            As[kk][ap] = v;
        }
        // ---- load B tile (coalesced) ----
#pragma unroll
        for (int kk = bk0; kk < BK; kk += 4) {
            Bs[kk][bo] = wT[(k0 + kk) * HCH + n0 + bo];
        }
        __syncthreads();

#pragma unroll
        for (int kk = 0; kk < BK; kk++) {
            float a[TM], bb[TN];
#pragma unroll
            for (int i = 0; i < TM; i++) a[i] = As[kk][ty * TM + i];
#pragma unroll
            for (int j = 0; j < TN; j++) bb[j] = Bs[kk][tx * TN + j];
#pragma unroll
            for (int i = 0; i < TM; i++)
#pragma unroll
                for (int j = 0; j < TN; j++)
                    acc[i][j] += a[i] * bb[j];
        }
        __syncthreads();
    }

    // ---- epilogue: bias (+ReLU), write NCHW ----
#pragma unroll
    for (int i = 0; i < TM; i++) {
        int pp = m0 + ty * TM + i;
        if (pp >= M) continue;
#pragma unroll
        for (int j = 0; j < TN; j++) {
            int oc = n0 + tx * TN + j;
            float v = acc[i][j] + bias[oc];
            if (RELU) v = fmaxf(v, 0.f);
            out[((size_t)b * HCH + oc) * M + pp] = v;
        }
    }
}

// ---------------------------------------------------------------------------
// Depthwise cross-correlation: per (b,c) plane, 29x29 input (x) 5x5 kernel
// -> 25x25 output. One block per plane, plane data staged in smem.
// ---------------------------------------------------------------------------
__global__ void xcorr_kernel(const float* __restrict__ s,
                             const float* __restrict__ k,
                             float* __restrict__ out)
{
    __shared__ float ss[29 * 29];
    __shared__ float kk[25];
    const int plane = blockIdx.x;        // b*256 + c
    const float* sp = s + (size_t)plane * (29 * 29);
    const float* kp = k + (size_t)plane * 25;
    const int tid = threadIdx.x;

    for (int i = tid; i < 29 * 29; i += 256) ss[i] = sp[i];
    if (tid < 25) kk[tid] = kp[tid];
    __syncthreads();

    for (int p = tid; p < 625; p += 256) {
        int y = p / 25, x = p % 25;
        float acc = 0.f;
#pragma unroll
        for (int u = 0; u < 5; u++)
#pragma unroll
            for (int v = 0; v < 5; v++)
                acc += ss[(y + u) * 29 + x + v] * kk[u * 5 + v];
        out[(size_t)plane * 625 + p] = acc;
    }
}

// ---------------------------------------------------------------------------
// Launch
// ---------------------------------------------------------------------------
extern "C" void kernel_launch(void* const* d_in, const int* in_sizes, int n_in,
                              void* d_out, int out_size)
{
    (void)in_sizes; (void)n_in; (void)out_size;
    const float* in_kernel = (const float*)d_in[0];
    const float* in_search = (const float*)d_in[1];
    const float* wk = (const float*)d_in[2];
    const float* gk = (const float*)d_in[3];
    const float* bk = (const float*)d_in[4];
    const float* mk = (const float*)d_in[5];
    const float* vk = (const float*)d_in[6];
    const float* ws = (const float*)d_in[7];
    const float* gs = (const float*)d_in[8];
    const float* bs = (const float*)d_in[9];
    const float* ms = (const float*)d_in[10];
    const float* vs = (const float*)d_in[11];
    const float* wh1 = (const float*)d_in[12];
    const float* gh  = (const float*)d_in[13];
    const float* bh  = (const float*)d_in[14];
    const float* mh  = (const float*)d_in[15];
    const float* vh  = (const float*)d_in[16];
    const float* wh2 = (const float*)d_in[17];
    const float* bh2 = (const float*)d_in[18];
    float* out = (float*)d_out;

    float *kbuf, *sbuf, *feat, *hbuf;
    float *wkT, *wsT, *wh1T, *wh2T, *biask, *biass, *biash;
    cudaGetSymbolAddress((void**)&kbuf,  g_kbuf);
    cudaGetSymbolAddress((void**)&sbuf,  g_sbuf);
    cudaGetSymbolAddress((void**)&feat,  g_feat);
    cudaGetSymbolAddress((void**)&hbuf,  g_hbuf);
    cudaGetSymbolAddress((void**)&wkT,   g_wkT);
    cudaGetSymbolAddress((void**)&wsT,   g_wsT);
    cudaGetSymbolAddress((void**)&wh1T,  g_wh1T);
    cudaGetSymbolAddress((void**)&wh2T,  g_wh2T);
    cudaGetSymbolAddress((void**)&biask, g_biask);
    cudaGetSymbolAddress((void**)&biass, g_biass);
    cudaGetSymbolAddress((void**)&biash, g_biash);

    // 1. fold BN into weights + transpose
    {
        int n3 = 2304 * HCH, n1 = 256 * HCH;
        fold_weights_bn<<<(n3 + 255) / 256, 256>>>(wk, gk, bk, mk, vk, wkT, biask, 2304);
        fold_weights_bn<<<(n3 + 255) / 256, 256>>>(ws, gs, bs, ms, vs, wsT, biass, 2304);
        fold_weights_bn<<<(n1 + 255) / 256, 256>>>(wh1, gh, bh, mh, vh, wh1T, biash, 256);
        transpose_w   <<<(n1 + 255) / 256, 256>>>(wh2, wh2T, 256);
    }

    // 2. kernel tower: [B,256,7,7] -> [B,256,5,5]   (M=25, tile BM=32)
    conv_gemm<3, 32, 2, true><<<dim3(1, 4, BATCH), 256>>>(
        in_kernel, wkT, biask, kbuf, 7, 7, 5, 5);

    // 3. search tower: [B,256,31,31] -> [B,256,29,29]   (M=841, 14 tiles)
    conv_gemm<3, 64, 4, true><<<dim3(14, 4, BATCH), 256>>>(
        in_search, wsT, biass, sbuf, 31, 31, 29, 29);

    // 4. depthwise xcorr -> [B,256,25,25]
    xcorr_kernel<<<BATCH * HCH, 256>>>(sbuf, kbuf, feat);

    // 5. head 1x1 + BN + ReLU   (M=625, 10 tiles)
    conv_gemm<1, 64, 4, true><<<dim3(10, 4, BATCH), 256>>>(
        feat, wh1T, biash, hbuf, 25, 25, 25, 25);

    // 6. head 1x1 + bias -> out
    conv_gemm<1, 64, 4, false><<<dim3(10, 4, BATCH), 256>>>(
        hbuf, wh2T, bh2, out, 25, 25, 25, 25);
}

// round 2
// speedup vs baseline: 2.4304x; 2.4304x over previous
#include <cuda_runtime.h>
#include <cuda_bf16.h>
#include <math.h>

#define BATCH 128
#define CIN   256
#define HCH   256

// ---------------- scratch ----------------
__device__ float g_kbuf[BATCH * HCH * 5 * 5];
__device__ float g_sbuf[BATCH * HCH * 29 * 29];
__device__ float g_feat[BATCH * HCH * 25 * 25];
__device__ float g_hbuf[BATCH * HCH * 25 * 25];
__device__ float g_wk[2304 * HCH];
__device__ float g_ws[2304 * HCH];
__device__ float g_wh1[256 * HCH];
__device__ float g_wh2[256 * HCH];
__device__ float g_biask[HCH];
__device__ float g_biass[HCH];
__device__ float g_biash[HCH];

// ---------------- helpers ----------------
__device__ __forceinline__ unsigned f2tf(float x) {
    unsigned u;
    asm("cvt.rna.tf32.f32 %0, %1;" : "=r"(u) : "f"(x));
    return u;
}

__device__ __forceinline__ void mma_tf32(float c[4], const unsigned a[4], const unsigned b[2]) {
    asm volatile(
        "mma.sync.aligned.m16n8k8.row.col.f32.tf32.tf32.f32 "
        "{%0,%1,%2,%3}, {%4,%5,%6,%7}, {%8,%9}, {%0,%1,%2,%3};"
        : "+f"(c[0]), "+f"(c[1]), "+f"(c[2]), "+f"(c[3])
        : "r"(a[0]), "r"(a[1]), "r"(a[2]), "r"(a[3]), "r"(b[0]), "r"(b[1]));
}

// Fold BN into weights (keep [O,K] layout), round weights to tf32.
__global__ void fold_bn_tf32(const float* __restrict__ w,
                             const float* __restrict__ gamma,
                             const float* __restrict__ beta,
                             const float* __restrict__ mean,
                             const float* __restrict__ var,
                             float* __restrict__ wOut,
                             float* __restrict__ biasOut, int K)
{
    int idx = blockIdx.x * blockDim.x + threadIdx.x;
    if (idx >= K * HCH) return;
    int oc = idx / K;
    float inv = rsqrtf(var[oc] + 1e-5f) * gamma[oc];
    wOut[idx] = __uint_as_float(f2tf(w[idx] * inv));
    if (idx - oc * K == 0) biasOut[oc] = beta[oc] - mean[oc] * inv;
}

__global__ void round_tf32(const float* __restrict__ w, float* __restrict__ wOut, int n)
{
    int idx = blockIdx.x * blockDim.x + threadIdx.x;
    if (idx < n) wOut[idx] = __uint_as_float(f2tf(w[idx]));
}

// ---------------------------------------------------------------------------
// Tensor-core implicit-GEMM conv (stride 1, VALID), tf32 mma.sync.
//   C[oc, n] = sum_k W[oc,k] * im2col[n,k],  n = b*PIX + p  (flattened)
// Block: 128(oc) x 128(n), BK=32. 8 warps, warp tile 64x32 (4x4 m16n8k8).
// Smem stride 36 -> conflict-free fragment loads (bank = 4g+c bijective).
// ---------------------------------------------------------------------------
template<int KS, int Hin, int Win, int Hout, int Wout, bool RELU>
__global__ void __launch_bounds__(256)
conv_mma(const float* __restrict__ in,    // [B, CIN, Hin, Win] fp32
         const float* __restrict__ wF,    // [HCH, K] tf32-rounded, BN-folded
         const float* __restrict__ bias,  // [HCH]
         float* __restrict__ out)         // [B, HCH, PIX] fp32
{
    constexpr int KK  = KS * KS;
    constexpr int K   = CIN * KK;
    constexpr int PIX = Hout * Wout;
    constexpr int HW  = Hin * Win;
    constexpr int BK  = 32;
    constexpr int LD  = BK + 4;   // 36

    __shared__ float As[128 * LD];
    __shared__ float Bs[128 * LD];

    const int tid  = threadIdx.x;
    const int lane = tid & 31;
    const int warp = tid >> 5;
    const int wm   = warp >> 2;        // 0..1
    const int wn   = warp & 3;         // 0..3
    const int g    = lane >> 2;        // 0..7
    const int c    = lane & 3;         // 0..3

    const int m0 = blockIdx.y * 128;   // oc base
    const int n0 = blockIdx.x * 128;   // flattened pixel base

    // A (weights) load mapping: 4 rows of 32, float4 along K
    const int arow = tid >> 3;              // 0..31
    const int acol = (tid & 7) << 2;        // 0,4,..28
    const float* aptr = wF + (size_t)(m0 + arow) * K + acol;

    // B (im2col) load mapping: n = tid%128, k-half = 16*(tid/128)
    const int bn  = tid & 127;
    const int bkh = (tid >> 7) << 4;        // 0 or 16
    const int gn  = n0 + bn;
    const int b   = gn / PIX;
    const int p   = gn - b * PIX;
    const int py  = p / Wout;
    const int px  = p - py * Wout;
    const float* inb_p = in + (size_t)b * CIN * HW + py * Win + px;

    float acc[4][4][4];
#pragma unroll
    for (int i = 0; i < 4; i++)
#pragma unroll
        for (int j = 0; j < 4; j++)
#pragma unroll
            for (int e = 0; e < 4; e++) acc[i][j][e] = 0.f;

    float4 pa[4];
    float  pb[16];

    auto loadA = [&](int k0) {
#pragma unroll
        for (int it = 0; it < 4; it++)
            pa[it] = *reinterpret_cast<const float4*>(aptr + k0 + (size_t)it * 32 * K);
    };
    auto loadB = [&](int k0) {
#pragma unroll
        for (int kk = 0; kk < 16; kk++) {
            int k = k0 + bkh + kk;
            if (KS == 1) {
                pb[kk] = inb_p[(size_t)k * HW];
            } else {
                int ic = k / KK;
                int r  = k - ic * KK;
                int u  = r / KS;
                int v  = r - u * KS;
                pb[kk] = inb_p[(size_t)ic * HW + u * Win + v];
            }
        }
    };

    loadA(0);
    loadB(0);

    const unsigned* Asu = reinterpret_cast<const unsigned*>(As);
    const unsigned* Bsu = reinterpret_cast<const unsigned*>(Bs);

    for (int k0 = 0; k0 < K; k0 += BK) {
        __syncthreads();
        // store staged tiles (weights already tf32; activations rounded here)
#pragma unroll
        for (int it = 0; it < 4; it++)
            *reinterpret_cast<float4*>(&As[(arow + 32 * it) * LD + acol]) = pa[it];
#pragma unroll
        for (int kk = 0; kk < 16; kk++)
            Bs[bn * LD + bkh + kk] = __uint_as_float(f2tf(pb[kk]));
        __syncthreads();

        if (k0 + BK < K) { loadA(k0 + BK); loadB(k0 + BK); }

#pragma unroll
        for (int ks = 0; ks < 4; ks++) {
            const int kb = ks * 8;
            unsigned afr[4][4], bfr[4][2];
#pragma unroll
            for (int i = 0; i < 4; i++) {
                int row = wm * 64 + i * 16 + g;
                afr[i][0] = Asu[row * LD + kb + c];
                afr[i][1] = Asu[(row + 8) * LD + kb + c];
                afr[i][2] = Asu[row * LD + kb + c + 4];
                afr[i][3] = Asu[(row + 8) * LD + kb + c + 4];
            }
#pragma unroll
            for (int j = 0; j < 4; j++) {
                int nn = wn * 32 + j * 8 + g;
                bfr[j][0] = Bsu[nn * LD + kb + c];
                bfr[j][1] = Bsu[nn * LD + kb + c + 4];
            }
#pragma unroll
            for (int i = 0; i < 4; i++)
#pragma unroll
                for (int j = 0; j < 4; j++)
                    mma_tf32(acc[i][j], afr[i], bfr[j]);
        }
    }

    // epilogue: bias (+ReLU), scatter to [b, oc, p]
#pragma unroll
    for (int i = 0; i < 4; i++) {
        int ocA = m0 + wm * 64 + i * 16 + g;
        int ocB = ocA + 8;
        float biA = bias[ocA];
        float biB = bias[ocB];
#pragma unroll
        for (int j = 0; j < 4; j++) {
            int nb = n0 + wn * 32 + j * 8 + c * 2;
#pragma unroll
            for (int e = 0; e < 4; e++) {
                int nn = nb + (e & 1);
                int oc = (e < 2) ? ocA : ocB;
                float v = acc[i][j][e] + ((e < 2) ? biA : biB);
                if (RELU) v = fmaxf(v, 0.f);
                int bb = nn / PIX;
                int pp = nn - bb * PIX;
                out[((size_t)bb * HCH + oc) * PIX + pp] = v;
            }
        }
    }
}

// ---------------------------------------------------------------------------
// Depthwise xcorr: 29x29 (x) 5x5 -> 25x25, fp32 exact. One block per plane.
// ---------------------------------------------------------------------------
__global__ void xcorr_kernel(const float* __restrict__ s,
                             const float* __restrict__ k,
                             float* __restrict__ out)
{
    __shared__ float ss[29 * 29];
    __shared__ float kk[25];
    const int plane = blockIdx.x;
    const float* sp = s + (size_t)plane * (29 * 29);
    const float* kp = k + (size_t)plane * 25;
    const int tid = threadIdx.x;

    for (int i = tid; i < 29 * 29; i += 256) ss[i] = sp[i];
    if (tid < 25) kk[tid] = kp[tid];
    __syncthreads();

    for (int p = tid; p < 625; p += 256) {
        int y = p / 25, x = p - (p / 25) * 25;
        float acc = 0.f;
#pragma unroll
        for (int u = 0; u < 5; u++)
#pragma unroll
            for (int v = 0; v < 5; v++)
                acc += ss[(y + u) * 29 + x + v] * kk[u * 5 + v];
        out[(size_t)plane * 625 + p] = acc;
    }
}

// ---------------------------------------------------------------------------
extern "C" void kernel_launch(void* const* d_in, const int* in_sizes, int n_in,
                              void* d_out, int out_size)
{
    (void)in_sizes; (void)n_in; (void)out_size;
    const float* in_kernel = (const float*)d_in[0];
    const float* in_search = (const float*)d_in[1];
    const float* wk = (const float*)d_in[2];
    const float* gk = (const float*)d_in[3];
    const float* bk = (const float*)d_in[4];
    const float* mk = (const float*)d_in[5];
    const float* vk = (const float*)d_in[6];
    const float* ws = (const float*)d_in[7];
    const float* gs = (const float*)d_in[8];
    const float* bs = (const float*)d_in[9];
    const float* ms = (const float*)d_in[10];
    const float* vs = (const float*)d_in[11];
    const float* wh1 = (const float*)d_in[12];
    const float* gh  = (const float*)d_in[13];
    const float* bh  = (const float*)d_in[14];
    const float* mh  = (const float*)d_in[15];
    const float* vh  = (const float*)d_in[16];
    const float* wh2 = (const float*)d_in[17];
    const float* bh2 = (const float*)d_in[18];
    float* out = (float*)d_out;

    float *kbuf, *sbuf, *feat, *hbuf, *wkF, *wsF, *wh1F, *wh2F, *biask, *biass, *biash;
    cudaGetSymbolAddress((void**)&kbuf,  g_kbuf);
    cudaGetSymbolAddress((void**)&sbuf,  g_sbuf);
    cudaGetSymbolAddress((void**)&feat,  g_feat);
    cudaGetSymbolAddress((void**)&hbuf,  g_hbuf);
    cudaGetSymbolAddress((void**)&wkF,   g_wk);
    cudaGetSymbolAddress((void**)&wsF,   g_ws);
    cudaGetSymbolAddress((void**)&wh1F,  g_wh1);
    cudaGetSymbolAddress((void**)&wh2F,  g_wh2);
    cudaGetSymbolAddress((void**)&biask, g_biask);
    cudaGetSymbolAddress((void**)&biass, g_biass);
    cudaGetSymbolAddress((void**)&biash, g_biash);

    // 1. fold BN + tf32-round weights
    {
        int n3 = 2304 * HCH, n1 = 256 * HCH;
        fold_bn_tf32<<<(n3 + 255) / 256, 256>>>(wk, gk, bk, mk, vk, wkF, biask, 2304);
        fold_bn_tf32<<<(n3 + 255) / 256, 256>>>(ws, gs, bs, ms, vs, wsF, biass, 2304);
        fold_bn_tf32<<<(n1 + 255) / 256, 256>>>(wh1, gh, bh, mh, vh, wh1F, biash, 256);
        round_tf32  <<<(n1 + 255) / 256, 256>>>(wh2, wh2F, n1);
    }

    // 2. kernel tower: [B,256,7,7] -> [B,256,5,5]   N = 128*25 = 3200
    conv_mma<3, 7, 7, 5, 5, true><<<dim3(25, 2), 256>>>(in_kernel, wkF, biask, kbuf);

    // 3. search tower: [B,256,31,31] -> [B,256,29,29]   N = 128*841 = 107648
    conv_mma<3, 31, 31, 29, 29, true><<<dim3(841, 2), 256>>>(in_search, wsF, biass, sbuf);

    // 4. depthwise xcorr -> [B,256,25,25]
    xcorr_kernel<<<BATCH * HCH, 256>>>(sbuf, kbuf, feat);

    // 5. head 1x1 + BN + ReLU   N = 128*625 = 80000
    conv_mma<1, 25, 25, 25, 25, true><<<dim3(625, 2), 256>>>(feat, wh1F, biash, hbuf);

    // 6. head 1x1 + bias -> out
    conv_mma<1, 25, 25, 25, 25, false><<<dim3(625, 2), 256>>>(hbuf, wh2F, bh2, out);
}

// round 4
// speedup vs baseline: 3.6718x; 1.5108x over previous
#include <cuda_runtime.h>
#include <cuda_bf16.h>
#include <cstdint>
#include <math.h>

#define BATCH 128
#define CIN   256
#define HCH   256

// ---------------- scratch ----------------
__device__ float g_kin [BATCH * CIN * 49];        // tf32-rounded kernel input
__device__ float g_sin [BATCH * CIN * 961];       // tf32-rounded search input
__device__ float g_kbuf[BATCH * HCH * 25];        // kernel tower out (fp32)
__device__ float g_sbuf[BATCH * HCH * 841];       // search tower out (fp32)
__device__ float g_feat[BATCH * HCH * 625];       // xcorr out (tf32-rounded)
__device__ float g_hbuf[BATCH * HCH * 625];       // head1 out (tf32-rounded)
__device__ float g_awk [2 * 288 * 1024];          // permuted weights
__device__ float g_aws [2 * 288 * 1024];
__device__ float g_awh1[2 * 32 * 1024];
__device__ float g_awh2[2 * 32 * 1024];
__device__ int   g_offk[2304];                    // im2col offset tables
__device__ int   g_offs[2304];
__device__ int   g_offh[256];
__device__ float g_biask[HCH];
__device__ float g_biass[HCH];
__device__ float g_biash[HCH];

// ---------------- helpers ----------------
__device__ __forceinline__ uint32_t smem_u32(const void* p) {
    uint32_t a;
    asm("{ .reg .u64 t; cvta.to.shared.u64 t, %1; cvt.u32.u64 %0, t; }" : "=r"(a) : "l"(p));
    return a;
}
__device__ __forceinline__ unsigned f2tf(float x) {
    unsigned u;
    asm("cvt.rna.tf32.f32 %0, %1;" : "=r"(u) : "f"(x));
    return u;
}
__device__ __forceinline__ void mma_tf32(float c[4], const unsigned a[4], const unsigned b[2]) {
    asm volatile(
        "mma.sync.aligned.m16n8k8.row.col.f32.tf32.tf32.f32 "
        "{%0,%1,%2,%3}, {%4,%5,%6,%7}, {%8,%9}, {%0,%1,%2,%3};"
        : "+f"(c[0]), "+f"(c[1]), "+f"(c[2]), "+f"(c[3])
        : "r"(a[0]), "r"(a[1]), "r"(a[2]), "r"(a[3]), "r"(b[0]), "r"(b[1]));
}

#define CP16(dst, src) \
    asm volatile("cp.async.ca.shared.global [%0], [%1], 16;" :: "r"(dst), "l"(src) : "memory")
#define CP4(dst, src) \
    asm volatile("cp.async.ca.shared.global [%0], [%1], 4;"  :: "r"(dst), "l"(src) : "memory")
#define CP_COMMIT() asm volatile("cp.async.commit_group;" ::: "memory")
#define CP_WAIT(n)  asm volatile("cp.async.wait_group %0;" :: "n"(n) : "memory")

#define LDS128(r0, r1, r2, r3, addr) \
    asm volatile("ld.shared.v4.b32 {%0,%1,%2,%3}, [%4];" \
        : "=r"(r0), "=r"(r1), "=r"(r2), "=r"(r3) : "r"(addr))
#define LDS64(r0, r1, addr) \
    asm volatile("ld.shared.v2.b32 {%0,%1}, [%2];" : "=r"(r0), "=r"(r1) : "r"(addr))

// ---------------- prep kernels ----------------
// im2col gmem-offset table: off[k] = (k/KK)*HW + ((k%KK)/KS)*Win + (k%KK)%KS
__global__ void fill_offT(int* t, int K, int KK, int KS, int HW, int Win)
{
    int k = blockIdx.x * blockDim.x + threadIdx.x;
    if (k >= K) return;
    int ic = k / KK, r = k - ic * KK, u = r / KS, v = r - u * KS;
    t[k] = ic * HW + u * Win + v;
}

// Fold BN + permute weights into fragment-atom order:
//  awOut[((mb*(K/8)+ki)*8 + mi)*128 + lane*4 + slot] = w[row, col] * inv(row)
//  row = mb*128 + mi*16 + (lane>>2) + (slot&1)*8
//  col = ki*8 + (lane&3) + (slot>>1)*4
__global__ void fold_bn_permute(const float* __restrict__ w,
                                const float* __restrict__ gamma,
                                const float* __restrict__ beta,
                                const float* __restrict__ mean,
                                const float* __restrict__ var,
                                float* __restrict__ awOut,
                                float* __restrict__ biasOut, int K, int hasBN)
{
    int o = blockIdx.x * blockDim.x + threadIdx.x;
    if (o < HCH && hasBN) {
        float inv = rsqrtf(var[o] + 1e-5f) * gamma[o];
        biasOut[o] = beta[o] - mean[o] * inv;
    }
    if (o >= 256 * K) return;
    int slot = o & 3, lane = (o >> 2) & 31, mi = (o >> 7) & 7, kia = o >> 10;
    int kb = K >> 3;
    int mb = kia / kb, ki = kia - mb * kb;
    int row = mb * 128 + mi * 16 + (lane >> 2) + (slot & 1) * 8;
    int col = ki * 8 + (lane & 3) + ((slot >> 1) & 1) * 4;
    float v = w[(size_t)row * K + col];
    if (hasBN) v *= rsqrtf(var[row] + 1e-5f) * gamma[row];
    awOut[o] = __uint_as_float(f2tf(v));
}

__global__ void round_buf(const float* __restrict__ s, float* __restrict__ d, int n)
{
    int i = blockIdx.x * blockDim.x + threadIdx.x;
    if (i < n) d[i] = __uint_as_float(f2tf(s[i]));
}

// ---------------------------------------------------------------------------
// tf32 mma.sync implicit-GEMM conv. CTA tile 128(oc) x 128(n), BK=32.
// 3-stage cp.async pipeline, fragment-order smem (LDS.128 / LDS.64 frags).
//  stage layout: A = 16384 B (4 katoms x 8 matoms x 32 lanes x 4 slots)
//                B = 16896 B (4 katoms x 16 natoms x (264 B padded atoms))
// ---------------------------------------------------------------------------
#define STAGE_BYTES 33280
#define SMEM_BYTES  (3 * STAGE_BYTES)

template<bool RELU, bool ROUND>
__global__ void __launch_bounds__(256)
conv_tc(const float* __restrict__ in,     // tf32-rounded activations
        const float* __restrict__ awF,    // permuted tf32 weights
        const int*   __restrict__ offT,   // im2col gmem offsets [K]
        const float* __restrict__ bias,
        float* __restrict__ out,
        int K, int HW, int Win, int Wout, int PIX, int awBlockStride)
{
    extern __shared__ char smem[];
    const uint32_t sb = smem_u32(smem);
    const int NITER = K >> 5;

    const int tid  = threadIdx.x;
    const int lane = tid & 31;
    const int warp = tid >> 5;
    const int wm = warp >> 2, wn = warp & 3;
    const int m0 = blockIdx.y * 128, n0 = blockIdx.x * 128;

    // B producer mapping: thread -> (pixel bn, k-half bkh)
    const int bn  = tid & 127;
    const int bkh = (tid >> 7) << 4;
    const int gn  = n0 + bn;
    const int b   = gn / PIX;
    const int p   = gn - b * PIX;
    const int py  = p / Wout;
    const int px  = p - py * Wout;
    const float* inb_p = in + (size_t)b * CIN * HW + py * Win + px;
    const uint32_t bOffBase =
        (uint32_t)((bkh >> 3) * 4224 + (bn >> 3) * 264 + (bn & 7) * 32);

    const float* awBlk = awF + (size_t)blockIdx.y * awBlockStride;

    auto issue = [&](int gi) {
        const uint32_t stage = sb + (uint32_t)(gi % 3) * STAGE_BYTES;
        // A tile: contiguous 16 KB (already fragment-ordered in gmem)
        const float* asrc = awBlk + (size_t)gi * 4096;
#pragma unroll
        for (int r = 0; r < 4; r++) {
            uint32_t d = stage + (uint32_t)((r * 256 + tid) * 16);
            CP16(d, asrc + (r * 256 + tid) * 4);
        }
        // B tile: per-element 4B gathers into fragment-order slots
        const int kBase = gi * 32 + bkh;
        const uint32_t bst = stage + 16384u + bOffBase;
#pragma unroll
        for (int kk = 0; kk < 16; kk++) {
            int off = __ldg(&offT[kBase + kk]);
            uint32_t d = bst + (uint32_t)((kk >> 3) * 4224 + (kk & 3) * 8 + ((kk >> 2) & 1) * 4);
            CP4(d, inb_p + off);
        }
        CP_COMMIT();
    };

    float acc[4][4][4];
#pragma unroll
    for (int i = 0; i < 4; i++)
#pragma unroll
        for (int j = 0; j < 4; j++)
#pragma unroll
            for (int e = 0; e < 4; e++) acc[i][j][e] = 0.f;

    issue(0);
    issue(1);

    for (int i = 0; i < NITER; i++) {
        if (i < NITER - 1) { CP_WAIT(1); } else { CP_WAIT(0); }
        __syncthreads();   // stage i visible to all; stage (i+2)%3 free
        if (i + 2 < NITER) issue(i + 2);

        const uint32_t sA = sb + (uint32_t)((i % 3)) * STAGE_BYTES;
        const uint32_t sB = sA + 16384u;
#pragma unroll
        for (int ks = 0; ks < 4; ks++) {
            unsigned afr[4][4], bfr[4][2];
#pragma unroll
            for (int ii = 0; ii < 4; ii++) {
                uint32_t a = sA + (uint32_t)((ks * 8 + wm * 4 + ii) * 512 + lane * 16);
                LDS128(afr[ii][0], afr[ii][1], afr[ii][2], afr[ii][3], a);
            }
#pragma unroll
            for (int j = 0; j < 4; j++) {
                uint32_t a = sB + (uint32_t)(ks * 4224 + (wn * 4 + j) * 264 + lane * 8);
                LDS64(bfr[j][0], bfr[j][1], a);
            }
#pragma unroll
            for (int ii = 0; ii < 4; ii++)
#pragma unroll
                for (int j = 0; j < 4; j++)
                    mma_tf32(acc[ii][j], afr[ii], bfr[j]);
        }
    }

    // epilogue: bias (+ReLU) (+tf32-round), scatter to [b, oc, p]
    const int g = lane >> 2, c = lane & 3;
#pragma unroll
    for (int ii = 0; ii < 4; ii++) {
        int ocA = m0 + wm * 64 + ii * 16 + g;
        int ocB = ocA + 8;
        float biA = bias[ocA];
        float biB = bias[ocB];
#pragma unroll
        for (int j = 0; j < 4; j++) {
            int nb = n0 + wn * 32 + j * 8 + c * 2;
#pragma unroll
            for (int e = 0; e < 4; e++) {
                int nn = nb + (e & 1);
                int oc = (e < 2) ? ocA : ocB;
                float v = acc[ii][j][e] + ((e < 2) ? biA : biB);
                if (RELU) v = fmaxf(v, 0.f);
                if (ROUND) v = __uint_as_float(f2tf(v));
                int bb = nn / PIX;
                int pp = nn - bb * PIX;
                out[((size_t)bb * HCH + oc) * PIX + pp] = v;
            }
        }
    }
}

// ---------------------------------------------------------------------------
// Depthwise xcorr: 29x29 (x) 5x5 -> 25x25, fp32 exact; output tf32-rounded
// (it is only consumed as a tf32 MMA operand downstream).
// ---------------------------------------------------------------------------
__global__ void xcorr_kernel(const float* __restrict__ s,
                             const float* __restrict__ k,
                             float* __restrict__ out)
{
    __shared__ float ss[29 * 29];
    __shared__ float kk[25];
    const int plane = blockIdx.x;
    const float* sp = s + (size_t)plane * (29 * 29);
    const float* kp = k + (size_t)plane * 25;
    const int tid = threadIdx.x;

    for (int i = tid; i < 29 * 29; i += 256) ss[i] = sp[i];
    if (tid < 25) kk[tid] = kp[tid];
    __syncthreads();

    for (int p = tid; p < 625; p += 256) {
        int y = p / 25, x = p - (p / 25) * 25;
        float acc = 0.f;
#pragma unroll
        for (int u = 0; u < 5; u++)
#pragma unroll
            for (int v = 0; v < 5; v++)
                acc += ss[(y + u) * 29 + x + v] * kk[u * 5 + v];
        out[(size_t)plane * 625 + p] = __uint_as_float(f2tf(acc));
    }
}

// ---------------------------------------------------------------------------
extern "C" void kernel_launch(void* const* d_in, const int* in_sizes, int n_in,
                              void* d_out, int out_size)
{
    (void)in_sizes; (void)n_in; (void)out_size;
    const float* in_kernel = (const float*)d_in[0];
    const float* in_search = (const float*)d_in[1];
    const float* wk = (const float*)d_in[2];
    const float* gk = (const float*)d_in[3];
    const float* bk = (const float*)d_in[4];
    const float* mk = (const float*)d_in[5];
    const float* vk = (const float*)d_in[6];
    const float* ws = (const float*)d_in[7];
    const float* gs = (const float*)d_in[8];
    const float* bs = (const float*)d_in[9];
    const float* ms = (const float*)d_in[10];
    const float* vs = (const float*)d_in[11];
    const float* wh1 = (const float*)d_in[12];
    const float* gh  = (const float*)d_in[13];
    const float* bh  = (const float*)d_in[14];
    const float* mh  = (const float*)d_in[15];
    const float* vh  = (const float*)d_in[16];
    const float* wh2 = (const float*)d_in[17];
    const float* bh2 = (const float*)d_in[18];
    float* out = (float*)d_out;

    float *kin, *sin_, *kbuf, *sbuf, *feat, *hbuf;
    float *awk, *aws, *awh1, *awh2, *biask, *biass, *biash;
    int *offk, *offs, *offh;
    cudaGetSymbolAddress((void**)&kin,   g_kin);
    cudaGetSymbolAddress((void**)&sin_,  g_sin);
    cudaGetSymbolAddress((void**)&kbuf,  g_kbuf);
    cudaGetSymbolAddress((void**)&sbuf,  g_sbuf);
    cudaGetSymbolAddress((void**)&feat,  g_feat);
    cudaGetSymbolAddress((void**)&hbuf,  g_hbuf);
    cudaGetSymbolAddress((void**)&awk,   g_awk);
    cudaGetSymbolAddress((void**)&aws,   g_aws);
    cudaGetSymbolAddress((void**)&awh1,  g_awh1);
    cudaGetSymbolAddress((void**)&awh2,  g_awh2);
    cudaGetSymbolAddress((void**)&offk,  g_offk);
    cudaGetSymbolAddress((void**)&offs,  g_offs);
    cudaGetSymbolAddress((void**)&offh,  g_offh);
    cudaGetSymbolAddress((void**)&biask, g_biask);
    cudaGetSymbolAddress((void**)&biass, g_biass);
    cudaGetSymbolAddress((void**)&biash, g_biash);

    cudaFuncSetAttribute(conv_tc<true, false>,
                         cudaFuncAttributeMaxDynamicSharedMemorySize, SMEM_BYTES);
    cudaFuncSetAttribute(conv_tc<true, true>,
                         cudaFuncAttributeMaxDynamicSharedMemorySize, SMEM_BYTES);
    cudaFuncSetAttribute(conv_tc<false, false>,
                         cudaFuncAttributeMaxDynamicSharedMemorySize, SMEM_BYTES);

    // ---- prep ----
    fill_offT<<<(2304 + 255) / 256, 256>>>(offk, 2304, 9, 3, 49, 7);
    fill_offT<<<(2304 + 255) / 256, 256>>>(offs, 2304, 9, 3, 961, 31);
    fill_offT<<<(256 + 255) / 256, 256>>>(offh, 256, 1, 1, 625, 25);

    {
        int n3 = 256 * 2304, n1 = 256 * 256;
        fold_bn_permute<<<(n3 + 255) / 256, 256>>>(wk, gk, bk, mk, vk, awk, biask, 2304, 1);
        fold_bn_permute<<<(n3 + 255) / 256, 256>>>(ws, gs, bs, ms, vs, aws, biass, 2304, 1);
        fold_bn_permute<<<(n1 + 255) / 256, 256>>>(wh1, gh, bh, mh, vh, awh1, biash, 256, 1);
        fold_bn_permute<<<(n1 + 255) / 256, 256>>>(wh2, gh, bh, mh, vh, awh2, nullptr, 256, 0);
    }

    {
        int nk = BATCH * CIN * 49, ns = BATCH * CIN * 961;
        round_buf<<<(nk + 255) / 256, 256>>>(in_kernel, kin, nk);
        round_buf<<<(ns + 255) / 256, 256>>>(in_search, sin_, ns);
    }

    // ---- pipeline ----
    // kernel tower: N = 3200 -> 25 tiles
    conv_tc<true, false><<<dim3(25, 2), 256, SMEM_BYTES>>>(
        kin, awk, offk, biask, kbuf, 2304, 49, 7, 5, 25, 294912);

    // search tower: N = 107648 -> 841 tiles
    conv_tc<true, false><<<dim3(841, 2), 256, SMEM_BYTES>>>(
        sin_, aws, offs, biass, sbuf, 2304, 961, 31, 29, 841, 294912);

    // depthwise xcorr (rounds feat to tf32)
    xcorr_kernel<<<BATCH * HCH, 256>>>(sbuf, kbuf, feat);

    // head 1x1 + BN + ReLU (rounds hbuf to tf32): N = 80000 -> 625 tiles
    conv_tc<true, true><<<dim3(625, 2), 256, SMEM_BYTES>>>(
        feat, awh1, offh, biash, hbuf, 256, 625, 25, 25, 625, 32768);

    // head 1x1 + bias -> out (full fp32 store)
    conv_tc<false, false><<<dim3(625, 2), 256, SMEM_BYTES>>>(
        hbuf, awh2, offh, bh2, out, 256, 625, 25, 25, 625, 32768);
}

// round 5
// speedup vs baseline: 5.3278x; 1.4510x over previous
#include <cuda_runtime.h>
#include <cuda_fp16.h>
#include <cstdint>
#include <math.h>

#define BATCH 128
#define CIN   256
#define HCH   256

// ---------------- scratch ----------------
__device__ __half   g_kin [BATCH * 49 * CIN];      // NHWC fp16 kernel input
__device__ __half   g_sin [BATCH * 961 * CIN];     // NHWC fp16 search input
__device__ float    g_kbuf[BATCH * HCH * 25];      // tower out NCHW fp32 (exact, for xcorr)
__device__ float    g_sbuf[BATCH * HCH * 841];
__device__ __half   g_feat[BATCH * 625 * HCH];     // xcorr out NHWC fp16
__device__ __half   g_hbuf[BATCH * 625 * HCH];     // head1 out NHWC fp16
__device__ uint32_t g_awk [294912];                // permuted f16x2 weights (towers: 256*2304/2)
__device__ uint32_t g_aws [294912];
__device__ uint32_t g_awh1[32768];                 // heads: 256*256/2
__device__ uint32_t g_awh2[32768];
__device__ float    g_biask[HCH];
__device__ float    g_biass[HCH];
__device__ float    g_biash[HCH];

// ---------------- helpers ----------------
__device__ __forceinline__ uint32_t smem_u32(const void* p) {
    uint32_t a;
    asm("{ .reg .u64 t; cvta.to.shared.u64 t, %1; cvt.u32.u64 %0, t; }" : "=r"(a) : "l"(p));
    return a;
}
__device__ __forceinline__ void mma_f16(float c[4], const unsigned a[4], const unsigned b[2]) {
    asm volatile(
        "mma.sync.aligned.m16n8k16.row.col.f32.f16.f16.f32 "
        "{%0,%1,%2,%3}, {%4,%5,%6,%7}, {%8,%9}, {%0,%1,%2,%3};"
        : "+f"(c[0]), "+f"(c[1]), "+f"(c[2]), "+f"(c[3])
        : "r"(a[0]), "r"(a[1]), "r"(a[2]), "r"(a[3]), "r"(b[0]), "r"(b[1]));
}

#define CP16(dst, src) \
    asm volatile("cp.async.ca.shared.global [%0], [%1], 16;" :: "r"(dst), "l"(src) : "memory")
#define CP_COMMIT() asm volatile("cp.async.commit_group;" ::: "memory")
#define CP_WAIT0()  asm volatile("cp.async.wait_group 0;" ::: "memory")

#define LDS128(r0, r1, r2, r3, addr) \
    asm volatile("ld.shared.v4.b32 {%0,%1,%2,%3}, [%4];" \
        : "=r"(r0), "=r"(r1), "=r"(r2), "=r"(r3) : "r"(addr))
#define LDS32(r0, addr) \
    asm volatile("ld.shared.b32 %0, [%1];" : "=r"(r0) : "r"(addr))

// ---------------- prep: NCHW fp32 -> NHWC fp16 ----------------
// grid (hwTiles, 8, B); block 256. 32c x 32hw tile via smem.
__global__ void nchw2nhwc(const float* __restrict__ in, __half* __restrict__ out, int HW)
{
    __shared__ float tile[32][33];
    const int hw0 = blockIdx.x * 32;
    const int c0  = blockIdx.y * 32;
    const int b   = blockIdx.z;
    const int tid = threadIdx.x;

    const int hwl = tid & 31;
    const int cl  = tid >> 5;          // 0..7
#pragma unroll
    for (int pass = 0; pass < 4; pass++) {
        int c = cl + pass * 8;
        int hw = hw0 + hwl;
        tile[c][hwl] = (hw < HW) ? in[((size_t)b * CIN + c0 + c) * HW + hw] : 0.f;
    }
    __syncthreads();

    const int hwo = tid >> 3;          // 0..31
    const int cq  = (tid & 7) * 4;
    if (hw0 + hwo < HW) {
        float v0 = tile[cq + 0][hwo];
        float v1 = tile[cq + 1][hwo];
        float v2 = tile[cq + 2][hwo];
        float v3 = tile[cq + 3][hwo];
        __half2 h0 = __floats2half2_rn(v0, v1);
        __half2 h1 = __floats2half2_rn(v2, v3);
        __half2* dst = reinterpret_cast<__half2*>(
            out + ((size_t)b * HW + hw0 + hwo) * CIN + c0 + cq);
        dst[0] = h0;
        dst[1] = h1;
    }
}

// ---------------- prep: fold BN + permute weights to f16x2 fragment order ----
// word layout: [mb][gi=K/32][ks(2)][mi(8)][lane(32)][slot(4)]
//  row = mb*128 + mi*16 + (lane>>2) + (slot&1)*8
//  k   = gi*32 + ks*16 + (lane&3)*2 + ((slot>>1)&1)*8 + h   (h = half 0/1)
// k-order: towers (KK=9): k = uv*256+ic -> src col = ic*9+uv; heads: col = k.
__global__ void permute_w(const float* __restrict__ w,
                          const float* __restrict__ gamma,
                          const float* __restrict__ beta,
                          const float* __restrict__ mean,
                          const float* __restrict__ var,
                          uint32_t* __restrict__ awOut,
                          float* __restrict__ biasOut,
                          int K, int KK, int hasBN)
{
    const int total = 256 * K / 2;
    int o = blockIdx.x * blockDim.x + threadIdx.x;
    if (o < 256 && hasBN) {
        float inv = rsqrtf(var[o] + 1e-5f) * gamma[o];
        biasOut[o] = beta[o] - mean[o] * inv;
    }
    if (o >= total) return;

    const int perMb = (K / 32) * 2048;
    int mb = o / perMb;
    int r  = o - mb * perMb;
    int gi = r >> 11;
    int r2 = r & 2047;
    int ks   = r2 >> 10;
    int mi   = (r2 >> 7) & 7;
    int lane = (r2 >> 2) & 31;
    int slot = r2 & 3;

    int row = mb * 128 + mi * 16 + (lane >> 2) + (slot & 1) * 8;
    int k0  = gi * 32 + ks * 16 + (lane & 3) * 2 + ((slot >> 1) & 1) * 8;

    float inv = hasBN ? (rsqrtf(var[row] + 1e-5f) * gamma[row]) : 1.f;

    uint32_t packed = 0;
#pragma unroll
    for (int h = 0; h < 2; h++) {
        int k = k0 + h;
        int col;
        if (KK == 9) { int uv = k >> 8; int ic = k & 255; col = ic * 9 + uv; }
        else col = k;
        float v = w[(size_t)row * K + col] * inv;
        __half hv = __float2half_rn(v);
        packed |= (uint32_t)__half_as_ushort(hv) << (h * 16);
    }
    awOut[o] = packed;
}

// ---------------------------------------------------------------------------
// fp16 m16n8k16 implicit-GEMM conv, NHWC activations.
// CTA tile 128(oc) x 128(n), BK=32. 2-stage cp.async double buffer.
// stage: A 8192 B ([ks][mi][lane][16B]) + B 10240 B ([n][80B k-row]).
// MODE 0: fp32 NCHW out; MODE 1: fp16 NHWC out.
// ---------------------------------------------------------------------------
#define STAGE 18432
#define SMEMB (2 * STAGE)

template<int KS, bool RELU, int MODE>
__global__ void __launch_bounds__(256)
conv_f16(const __half* __restrict__ in,     // NHWC fp16
         const uint32_t* __restrict__ aw,   // permuted f16x2 weights
         const float* __restrict__ bias,
         float* __restrict__ outF,          // MODE 0
         __half* __restrict__ outH,         // MODE 1
         int K, int Hin, int Win, int Wout, int PIX)
{
    extern __shared__ char smem[];
    const uint32_t sb = smem_u32(smem);
    const int NITER = K >> 5;

    const int tid  = threadIdx.x;
    const int lane = tid & 31;
    const int warp = tid >> 5;
    const int wm = warp >> 2, wn = warp & 3;
    const int g = lane >> 2, c = lane & 3;
    const int m0 = blockIdx.y * 128, n0 = blockIdx.x * 128;

    // B producer mapping
    const int bn  = tid & 127;
    const int bkh = (tid >> 7) << 4;       // 0 or 16
    const int gn  = n0 + bn;
    const __half* inb;
    if (KS == 1) {
        inb = in + (size_t)gn * 256;
    } else {
        const int b  = gn / PIX;
        const int p  = gn - b * PIX;
        const int py = p / Wout;
        const int px = p - py * Wout;
        inb = in + ((size_t)(b * Hin + py) * Win + px) * 256;
    }

    const uint32_t* awBlk = aw + (size_t)blockIdx.y * (K / 32) * 2048;

    auto issue = [&](int gi) {
        const uint32_t stage = sb + (uint32_t)(gi & 1) * STAGE;
        // A tile: 8KB linear
        const uint32_t* asrc = awBlk + (size_t)gi * 2048 + tid * 8;
        CP16(stage + tid * 32,      asrc);
        CP16(stage + tid * 32 + 16, asrc + 4);
        // B tile: 16 contiguous channels (32B) per thread
        int koff;
        if (KS == 1) {
            koff = gi * 32 + bkh;
        } else {
            int uv = gi >> 3;
            int u = uv / 3, v = uv - u * 3;
            koff = (u * Win + v) * 256 + (gi & 7) * 32 + bkh;
        }
        const __half* bsrc = inb + koff;
        uint32_t bd = stage + 8192u + (uint32_t)bn * 80 + bkh * 2;
        CP16(bd,      bsrc);
        CP16(bd + 16, bsrc + 8);
        CP_COMMIT();
    };

    float acc[4][4][4];
#pragma unroll
    for (int i = 0; i < 4; i++)
#pragma unroll
        for (int j = 0; j < 4; j++)
#pragma unroll
            for (int e = 0; e < 4; e++) acc[i][j][e] = 0.f;

    issue(0);

    for (int i = 0; i < NITER; i++) {
        CP_WAIT0();
        __syncthreads();
        if (i + 1 < NITER) issue(i + 1);

        const uint32_t sA = sb + (uint32_t)(i & 1) * STAGE;
        const uint32_t sB = sA + 8192u;
#pragma unroll
        for (int ks = 0; ks < 2; ks++) {
            unsigned afr[4][4], bfr[4][2];
#pragma unroll
            for (int ii = 0; ii < 4; ii++) {
                uint32_t a = sA + (uint32_t)((ks * 8 + wm * 4 + ii) << 9) + lane * 16;
                LDS128(afr[ii][0], afr[ii][1], afr[ii][2], afr[ii][3], a);
            }
#pragma unroll
            for (int j = 0; j < 4; j++) {
                uint32_t a = sB + (uint32_t)(((wn * 4 + j) * 8 + g) * 80 + ks * 32 + c * 4);
                LDS32(bfr[j][0], a);
                LDS32(bfr[j][1], a + 16);
            }
#pragma unroll
            for (int ii = 0; ii < 4; ii++)
#pragma unroll
                for (int j = 0; j < 4; j++)
                    mma_f16(acc[ii][j], afr[ii], bfr[j]);
        }
    }

    // epilogue
#pragma unroll
    for (int ii = 0; ii < 4; ii++) {
        int ocA = m0 + wm * 64 + ii * 16 + g;
        int ocB = ocA + 8;
        float biA = bias[ocA];
        float biB = bias[ocB];
#pragma unroll
        for (int j = 0; j < 4; j++) {
            int nb = n0 + wn * 32 + j * 8 + c * 2;
#pragma unroll
            for (int e = 0; e < 4; e++) {
                int nn = nb + (e & 1);
                int oc = (e < 2) ? ocA : ocB;
                float v = acc[ii][j][e] + ((e < 2) ? biA : biB);
                if (RELU) v = fmaxf(v, 0.f);
                if (MODE == 0) {
                    int bb = nn / PIX;
                    int pp = nn - bb * PIX;
                    outF[((size_t)bb * HCH + oc) * PIX + pp] = v;
                } else {
                    outH[(size_t)nn * 256 + oc] = __float2half_rn(v);
                }
            }
        }
    }
}

// ---------------------------------------------------------------------------
// Depthwise xcorr: fp32 exact, in NCHW fp32, out NHWC fp16.
// Block = (b, 16-channel group). Dyn smem: 16 planes fp32 + 16 kernels.
// ---------------------------------------------------------------------------
#define XC_SMEM (16 * 841 * 4 + 16 * 25 * 4)

__global__ void xcorr_kernel(const float* __restrict__ s,
                             const float* __restrict__ k,
                             __half* __restrict__ feat)
{
    extern __shared__ float xs[];       // [16][841] then [16][25]
    float* ss = xs;
    float* kk = xs + 16 * 841;
    const int cg = blockIdx.x & 15;
    const int b  = blockIdx.x >> 4;
    const int tid = threadIdx.x;

    const float* sp = s + ((size_t)b * 256 + cg * 16) * 841;
    const float* kp = k + ((size_t)b * 256 + cg * 16) * 25;
    for (int i = tid; i < 16 * 841; i += 256) ss[i] = sp[i];
    for (int i = tid; i < 16 * 25; i += 256) kk[i] = kp[i];
    __syncthreads();

    const int c  = tid & 15;
    const int p0 = tid >> 4;
    const float* sc = ss + c * 841;
    const float* kc = kk + c * 25;
    for (int p = p0; p < 625; p += 16) {
        int y = p / 25, x = p - (p / 25) * 25;
        float acc = 0.f;
#pragma unroll
        for (int u = 0; u < 5; u++)
#pragma unroll
            for (int v = 0; v < 5; v++)
                acc += sc[(y + u) * 29 + x + v] * kc[u * 5 + v];
        feat[((size_t)b * 625 + p) * 256 + cg * 16 + c] = __float2half_rn(acc);
    }
}

// ---------------------------------------------------------------------------
extern "C" void kernel_launch(void* const* d_in, const int* in_sizes, int n_in,
                              void* d_out, int out_size)
{
    (void)in_sizes; (void)n_in; (void)out_size;
    const float* in_kernel = (const float*)d_in[0];
    const float* in_search = (const float*)d_in[1];
    const float* wk = (const float*)d_in[2];
    const float* gk = (const float*)d_in[3];
    const float* bk = (const float*)d_in[4];
    const float* mk = (const float*)d_in[5];
    const float* vk = (const float*)d_in[6];
    const float* ws = (const float*)d_in[7];
    const float* gs = (const float*)d_in[8];
    const float* bs = (const float*)d_in[9];
    const float* ms = (const float*)d_in[10];
    const float* vs = (const float*)d_in[11];
    const float* wh1 = (const float*)d_in[12];
    const float* gh  = (const float*)d_in[13];
    const float* bh  = (const float*)d_in[14];
    const float* mh  = (const float*)d_in[15];
    const float* vh  = (const float*)d_in[16];
    const float* wh2 = (const float*)d_in[17];
    const float* bh2 = (const float*)d_in[18];
    float* out = (float*)d_out;

    __half *kin, *sin_, *feat, *hbuf;
    float *kbuf, *sbuf, *biask, *biass, *biash;
    uint32_t *awk, *aws, *awh1, *awh2;
    cudaGetSymbolAddress((void**)&kin,   g_kin);
    cudaGetSymbolAddress((void**)&sin_,  g_sin);
    cudaGetSymbolAddress((void**)&kbuf,  g_kbuf);
    cudaGetSymbolAddress((void**)&sbuf,  g_sbuf);
    cudaGetSymbolAddress((void**)&feat,  g_feat);
    cudaGetSymbolAddress((void**)&hbuf,  g_hbuf);
    cudaGetSymbolAddress((void**)&awk,   g_awk);
    cudaGetSymbolAddress((void**)&aws,   g_aws);
    cudaGetSymbolAddress((void**)&awh1,  g_awh1);
    cudaGetSymbolAddress((void**)&awh2,  g_awh2);
    cudaGetSymbolAddress((void**)&biask, g_biask);
    cudaGetSymbolAddress((void**)&biass, g_biass);
    cudaGetSymbolAddress((void**)&biash, g_biash);

    cudaFuncSetAttribute(conv_f16<3, true, 0>,
                         cudaFuncAttributeMaxDynamicSharedMemorySize, SMEMB);
    cudaFuncSetAttribute(conv_f16<1, true, 1>,
                         cudaFuncAttributeMaxDynamicSharedMemorySize, SMEMB);
    cudaFuncSetAttribute(conv_f16<1, false, 0>,
                         cudaFuncAttributeMaxDynamicSharedMemorySize, SMEMB);
    cudaFuncSetAttribute(xcorr_kernel,
                         cudaFuncAttributeMaxDynamicSharedMemorySize, XC_SMEM);

    // ---- prep ----
    nchw2nhwc<<<dim3(2, 8, BATCH), 256>>>(in_kernel, kin, 49);
    nchw2nhwc<<<dim3(31, 8, BATCH), 256>>>(in_search, sin_, 961);

    permute_w<<<(294912 + 255) / 256, 256>>>(wk, gk, bk, mk, vk, awk, biask, 2304, 9, 1);
    permute_w<<<(294912 + 255) / 256, 256>>>(ws, gs, bs, ms, vs, aws, biass, 2304, 9, 1);
    permute_w<<<(32768 + 255) / 256, 256>>>(wh1, gh, bh, mh, vh, awh1, biash, 256, 1, 1);
    permute_w<<<(32768 + 255) / 256, 256>>>(wh2, nullptr, nullptr, nullptr, nullptr,
                                            awh2, nullptr, 256, 1, 0);

    // ---- towers ----
    conv_f16<3, true, 0><<<dim3(25, 2), 256, SMEMB>>>(
        kin, awk, biask, kbuf, nullptr, 2304, 7, 7, 5, 25);
    conv_f16<3, true, 0><<<dim3(841, 2), 256, SMEMB>>>(
        sin_, aws, biass, sbuf, nullptr, 2304, 31, 31, 29, 841);

    // ---- xcorr (exact fp32 -> fp16 NHWC) ----
    xcorr_kernel<<<BATCH * 16, 256, XC_SMEM>>>(sbuf, kbuf, feat);

    // ---- heads ----
    conv_f16<1, true, 1><<<dim3(625, 2), 256, SMEMB>>>(
        feat, awh1, biash, nullptr, hbuf, 256, 1, 1, 25, 625);
    conv_f16<1, false, 0><<<dim3(625, 2), 256, SMEMB>>>(
        hbuf, awh2, bh2, out, nullptr, 256, 1, 1, 25, 625);
}

// round 6
// speedup vs baseline: 5.5313x; 1.0382x over previous
#include <cuda_runtime.h>
#include <cuda_fp16.h>
#include <cstdint>
#include <math.h>

#define BATCH 128
#define CIN   256
#define HCH   256

// ---------------- scratch ----------------
__device__ __half   g_kin [BATCH * 49 * CIN];      // NHWC fp16 kernel input
__device__ __half   g_sin [BATCH * 961 * CIN];     // NHWC fp16 search input
__device__ float    g_kbuf[BATCH * HCH * 25];      // tower out NCHW fp32 (exact, for xcorr)
__device__ float    g_sbuf[BATCH * HCH * 841];
__device__ __half   g_feat[BATCH * 625 * HCH];     // xcorr out NHWC fp16
__device__ __half   g_hbuf[BATCH * 625 * HCH];     // head1 out NHWC fp16
__device__ uint32_t g_awk [294912];                // permuted f16x2 weights
__device__ uint32_t g_aws [294912];
__device__ uint32_t g_awh1[32768];
__device__ uint32_t g_awh2[32768];
__device__ float    g_biask[HCH];
__device__ float    g_biass[HCH];
__device__ float    g_biash[HCH];

// ---------------- helpers ----------------
__device__ __forceinline__ uint32_t smem_u32(const void* p) {
    uint32_t a;
    asm("{ .reg .u64 t; cvta.to.shared.u64 t, %1; cvt.u32.u64 %0, t; }" : "=r"(a) : "l"(p));
    return a;
}
__device__ __forceinline__ void mma_f16(float c[4], const unsigned a[4], const unsigned b[2]) {
    asm volatile(
        "mma.sync.aligned.m16n8k16.row.col.f32.f16.f16.f32 "
        "{%0,%1,%2,%3}, {%4,%5,%6,%7}, {%8,%9}, {%0,%1,%2,%3};"
        : "+f"(c[0]), "+f"(c[1]), "+f"(c[2]), "+f"(c[3])
        : "r"(a[0]), "r"(a[1]), "r"(a[2]), "r"(a[3]), "r"(b[0]), "r"(b[1]));
}

#define CP16(dst, src) \
    asm volatile("cp.async.ca.shared.global [%0], [%1], 16;" :: "r"(dst), "l"(src) : "memory")
#define CP_COMMIT() asm volatile("cp.async.commit_group;" ::: "memory")
#define CP_WAIT0()  asm volatile("cp.async.wait_group 0;" ::: "memory")

#define LDS128(r0, r1, r2, r3, addr) \
    asm volatile("ld.shared.v4.b32 {%0,%1,%2,%3}, [%4];" \
        : "=r"(r0), "=r"(r1), "=r"(r2), "=r"(r3) : "r"(addr))
#define LDS32(r0, addr) \
    asm volatile("ld.shared.b32 %0, [%1];" : "=r"(r0) : "r"(addr))

// ---------------- prep: NCHW fp32 -> NHWC fp16 ----------------
__global__ void nchw2nhwc(const float* __restrict__ in, __half* __restrict__ out, int HW)
{
    __shared__ float tile[32][33];
    const int hw0 = blockIdx.x * 32;
    const int c0  = blockIdx.y * 32;
    const int b   = blockIdx.z;
    const int tid = threadIdx.x;

    const int hwl = tid & 31;
    const int cl  = tid >> 5;
#pragma unroll
    for (int pass = 0; pass < 4; pass++) {
        int c = cl + pass * 8;
        int hw = hw0 + hwl;
        tile[c][hwl] = (hw < HW) ? in[((size_t)b * CIN + c0 + c) * HW + hw] : 0.f;
    }
    __syncthreads();

    const int hwo = tid >> 3;
    const int cq  = (tid & 7) * 4;
    if (hw0 + hwo < HW) {
        __half2 h0 = __floats2half2_rn(tile[cq + 0][hwo], tile[cq + 1][hwo]);
        __half2 h1 = __floats2half2_rn(tile[cq + 2][hwo], tile[cq + 3][hwo]);
        __half2* dst = reinterpret_cast<__half2*>(
            out + ((size_t)b * HW + hw0 + hwo) * CIN + c0 + cq);
        dst[0] = h0;
        dst[1] = h1;
    }
}

// ---------------- prep: fold BN + permute weights (fragment order) ----------
__global__ void permute_w(const float* __restrict__ w,
                          const float* __restrict__ gamma,
                          const float* __restrict__ beta,
                          const float* __restrict__ mean,
                          const float* __restrict__ var,
                          uint32_t* __restrict__ awOut,
                          float* __restrict__ biasOut,
                          int K, int KK, int hasBN)
{
    const int total = 256 * K / 2;
    int o = blockIdx.x * blockDim.x + threadIdx.x;
    if (o < 256 && hasBN) {
        float inv = rsqrtf(var[o] + 1e-5f) * gamma[o];
        biasOut[o] = beta[o] - mean[o] * inv;
    }
    if (o >= total) return;

    const int perMb = (K / 32) * 2048;
    int mb = o / perMb;
    int r  = o - mb * perMb;
    int gi = r >> 11;
    int r2 = r & 2047;
    int ks   = r2 >> 10;
    int mi   = (r2 >> 7) & 7;
    int lane = (r2 >> 2) & 31;
    int slot = r2 & 3;

    int row = mb * 128 + mi * 16 + (lane >> 2) + (slot & 1) * 8;
    int k0  = gi * 32 + ks * 16 + (lane & 3) * 2 + ((slot >> 1) & 1) * 8;

    float inv = hasBN ? (rsqrtf(var[row] + 1e-5f) * gamma[row]) : 1.f;

    uint32_t packed = 0;
#pragma unroll
    for (int h = 0; h < 2; h++) {
        int k = k0 + h;
        int col;
        if (KK == 9) { int uv = k >> 8; int ic = k & 255; col = ic * 9 + uv; }
        else col = k;
        float v = w[(size_t)row * K + col] * inv;
        __half hv = __float2half_rn(v);
        packed |= (uint32_t)__half_as_ushort(hv) << (h * 16);
    }
    awOut[o] = packed;
}

// ---------------------------------------------------------------------------
// fp16 m16n8k16 implicit-GEMM conv body, NHWC activations.
// CTA tile 128(oc) x 128(n), BK=32, 2-stage cp.async.
// Epilogue staged through smem for fully-coalesced stores.
// MODE 0: fp32 NCHW out; MODE 1: fp16 NHWC out.
// ---------------------------------------------------------------------------
#define STAGE 18432
#define SMEM_PIPE   (2 * STAGE)            // 36864
#define SMEM_EPI_F  (128 * 136 * 4)        // 69632
#define SMEM_TOWERS SMEM_EPI_F
#define SMEM_HEAD1  SMEM_PIPE
#define SMEM_HEAD2  SMEM_EPI_F

template<int KS, bool RELU, int MODE>
__device__ __forceinline__ void
conv_body(const __half* __restrict__ in,
          const uint32_t* __restrict__ aw,
          const float* __restrict__ bias,
          float* __restrict__ outF,
          __half* __restrict__ outH,
          int K, int Hin, int Win, int Wout, int PIX, int tileX, int mb)
{
    extern __shared__ char smem[];
    const uint32_t sb = smem_u32(smem);
    const int NITER = K >> 5;

    const int tid  = threadIdx.x;
    const int lane = tid & 31;
    const int warp = tid >> 5;
    const int wm = warp >> 2, wn = warp & 3;
    const int g = lane >> 2, c = lane & 3;
    const int m0 = mb * 128, n0 = tileX * 128;

    // B producer mapping
    const int bn  = tid & 127;
    const int bkh = (tid >> 7) << 4;
    const int gn  = n0 + bn;
    const __half* inb;
    if (KS == 1) {
        inb = in + (size_t)gn * 256;
    } else {
        const int b  = gn / PIX;
        const int p  = gn - b * PIX;
        const int py = p / Wout;
        const int px = p - py * Wout;
        inb = in + ((size_t)(b * Hin + py) * Win + px) * 256;
    }

    const uint32_t* awBlk = aw + (size_t)mb * (K / 32) * 2048;

    auto issue = [&](int gi) {
        const uint32_t stg = sb + (uint32_t)(gi & 1) * STAGE;
        const uint32_t* asrc = awBlk + (size_t)gi * 2048 + tid * 8;
        CP16(stg + tid * 32,      asrc);
        CP16(stg + tid * 32 + 16, asrc + 4);
        int koff;
        if (KS == 1) {
            koff = gi * 32 + bkh;
        } else {
            int uv = gi >> 3;
            int u = uv / 3, v = uv - u * 3;
            koff = (u * Win + v) * 256 + (gi & 7) * 32 + bkh;
        }
        const __half* bsrc = inb + koff;
        uint32_t bd = stg + 8192u + (uint32_t)bn * 80 + bkh * 2;
        CP16(bd,      bsrc);
        CP16(bd + 16, bsrc + 8);
        CP_COMMIT();
    };

    float acc[4][4][4];
#pragma unroll
    for (int i = 0; i < 4; i++)
#pragma unroll
        for (int j = 0; j < 4; j++)
#pragma unroll
            for (int e = 0; e < 4; e++) acc[i][j][e] = 0.f;

    issue(0);

    for (int i = 0; i < NITER; i++) {
        CP_WAIT0();
        __syncthreads();
        if (i + 1 < NITER) issue(i + 1);

        const uint32_t sA = sb + (uint32_t)(i & 1) * STAGE;
        const uint32_t sB = sA + 8192u;
#pragma unroll
        for (int ks = 0; ks < 2; ks++) {
            unsigned afr[4][4], bfr[4][2];
#pragma unroll
            for (int ii = 0; ii < 4; ii++) {
                uint32_t a = sA + (uint32_t)((ks * 8 + wm * 4 + ii) << 9) + lane * 16;
                LDS128(afr[ii][0], afr[ii][1], afr[ii][2], afr[ii][3], a);
            }
#pragma unroll
            for (int j = 0; j < 4; j++) {
                uint32_t a = sB + (uint32_t)(((wn * 4 + j) * 8 + g) * 80 + ks * 32 + c * 4);
                LDS32(bfr[j][0], a);
                LDS32(bfr[j][1], a + 16);
            }
#pragma unroll
            for (int ii = 0; ii < 4; ii++)
#pragma unroll
                for (int j = 0; j < 4; j++)
                    mma_f16(acc[ii][j], afr[ii], bfr[j]);
        }
    }

    // ---- staged, coalesced epilogue ----
    __syncthreads();   // pipeline smem now reusable

    if (MODE == 0) {
        float* st = reinterpret_cast<float*>(smem);
#pragma unroll
        for (int ii = 0; ii < 4; ii++) {
            int ocl = wm * 64 + ii * 16 + g;
            float biA = bias[m0 + ocl];
            float biB = bias[m0 + ocl + 8];
#pragma unroll
            for (int j = 0; j < 4; j++) {
                int nl = wn * 32 + j * 8 + c * 2;
#pragma unroll
                for (int e = 0; e < 4; e++) {
                    float v = acc[ii][j][e] + ((e < 2) ? biA : biB);
                    if (RELU) v = fmaxf(v, 0.f);
                    st[(ocl + ((e < 2) ? 0 : 8)) * 136 + nl + (e & 1)] = v;
                }
            }
        }
        __syncthreads();
#pragma unroll
        for (int r = 0; r < 16; r++) {
            int id  = tid + 256 * r;
            int ocl = id >> 5;
            int nq  = (id & 31) * 4;
            float4 vv = *reinterpret_cast<const float4*>(&st[ocl * 136 + nq]);
            int oc = m0 + ocl;
            float vs[4] = {vv.x, vv.y, vv.z, vv.w};
#pragma unroll
            for (int q = 0; q < 4; q++) {
                int nn = n0 + nq + q;
                int bb = nn / PIX;
                int pp = nn - bb * PIX;
                outF[((size_t)bb * HCH + oc) * PIX + pp] = vs[q];
            }
        }
    } else {
        __half* st = reinterpret_cast<__half*>(smem);
#pragma unroll
        for (int ii = 0; ii < 4; ii++) {
            int ocl = wm * 64 + ii * 16 + g;
            float biA = bias[m0 + ocl];
            float biB = bias[m0 + ocl + 8];
#pragma unroll
            for (int j = 0; j < 4; j++) {
                int nl = wn * 32 + j * 8 + c * 2;
#pragma unroll
                for (int e = 0; e < 4; e++) {
                    float v = acc[ii][j][e] + ((e < 2) ? biA : biB);
                    if (RELU) v = fmaxf(v, 0.f);
                    st[(nl + (e & 1)) * 144 + ocl + ((e < 2) ? 0 : 8)] = __float2half_rn(v);
                }
            }
        }
        __syncthreads();
#pragma unroll
        for (int r = 0; r < 8; r++) {
            int id = tid + 256 * r;
            int n  = id >> 4;
            int ch = (id & 15) * 8;
            uint4 vv = *reinterpret_cast<const uint4*>(&st[n * 144 + ch]);
            *reinterpret_cast<uint4*>(&outH[(size_t)(n0 + n) * 256 + m0 + ch]) = vv;
        }
    }
}

// ---- merged towers: search tiles [0,841), kernel tiles [841,866) ----
__global__ void __launch_bounds__(256)
towers_kernel(const __half* __restrict__ sIn, const uint32_t* __restrict__ sAw,
              const float* __restrict__ sBias, float* __restrict__ sOut,
              const __half* __restrict__ kIn, const uint32_t* __restrict__ kAw,
              const float* __restrict__ kBias, float* __restrict__ kOut)
{
    if (blockIdx.x < 841)
        conv_body<3, true, 0>(sIn, sAw, sBias, sOut, nullptr,
                              2304, 31, 31, 29, 841, blockIdx.x, blockIdx.y);
    else
        conv_body<3, true, 0>(kIn, kAw, kBias, kOut, nullptr,
                              2304, 7, 7, 5, 25, blockIdx.x - 841, blockIdx.y);
}

// ---- head kernels (1x1) ----
template<bool RELU, int MODE>
__global__ void __launch_bounds__(256)
head_kernel(const __half* __restrict__ in, const uint32_t* __restrict__ aw,
            const float* __restrict__ bias, float* __restrict__ outF,
            __half* __restrict__ outH)
{
    conv_body<1, RELU, MODE>(in, aw, bias, outF, outH,
                             256, 1, 1, 25, 625, blockIdx.x, blockIdx.y);
}

// ---------------------------------------------------------------------------
// Depthwise xcorr: fp32 exact, NCHW fp32 in, NHWC fp16 out.
// ---------------------------------------------------------------------------
#define XC_SMEM (16 * 841 * 4 + 16 * 25 * 4)

__global__ void xcorr_kernel(const float* __restrict__ s,
                             const float* __restrict__ k,
                             __half* __restrict__ feat)
{
    extern __shared__ float xs[];
    float* ss = xs;
    float* kk = xs + 16 * 841;
    const int cg = blockIdx.x & 15;
    const int b  = blockIdx.x >> 4;
    const int tid = threadIdx.x;

    const float* sp = s + ((size_t)b * 256 + cg * 16) * 841;
    const float* kp = k + ((size_t)b * 256 + cg * 16) * 25;
    for (int i = tid; i < 16 * 841; i += 256) ss[i] = sp[i];
    for (int i = tid; i < 16 * 25; i += 256) kk[i] = kp[i];
    __syncthreads();

    const int c  = tid & 15;
    const int p0 = tid >> 4;
    const float* sc = ss + c * 841;
    const float* kc = kk + c * 25;
    for (int p = p0; p < 625; p += 16) {
        int y = p / 25, x = p - (p / 25) * 25;
        float acc = 0.f;
#pragma unroll
        for (int u = 0; u < 5; u++)
#pragma unroll
            for (int v = 0; v < 5; v++)
                acc += sc[(y + u) * 29 + x + v] * kc[u * 5 + v];
        feat[((size_t)b * 625 + p) * 256 + cg * 16 + c] = __float2half_rn(acc);
    }
}

// ---------------------------------------------------------------------------
extern "C" void kernel_launch(void* const* d_in, const int* in_sizes, int n_in,
                              void* d_out, int out_size)
{
    (void)in_sizes; (void)n_in; (void)out_size;
    const float* in_kernel = (const float*)d_in[0];
    const float* in_search = (const float*)d_in[1];
    const float* wk = (const float*)d_in[2];
    const float* gk = (const float*)d_in[3];
    const float* bk = (const float*)d_in[4];
    const float* mk = (const float*)d_in[5];
    const float* vk = (const float*)d_in[6];
    const float* ws = (const float*)d_in[7];
    const float* gs = (const float*)d_in[8];
    const float* bs = (const float*)d_in[9];
    const float* ms = (const float*)d_in[10];
    const float* vs = (const float*)d_in[11];
    const float* wh1 = (const float*)d_in[12];
    const float* gh  = (const float*)d_in[13];
    const float* bh  = (const float*)d_in[14];
    const float* mh  = (const float*)d_in[15];
    const float* vh  = (const float*)d_in[16];
    const float* wh2 = (const float*)d_in[17];
    const float* bh2 = (const float*)d_in[18];
    float* out = (float*)d_out;

    __half *kin, *sin_, *feat, *hbuf;
    float *kbuf, *sbuf, *biask, *biass, *biash;
    uint32_t *awk, *aws, *awh1, *awh2;
    cudaGetSymbolAddress((void**)&kin,   g_kin);
    cudaGetSymbolAddress((void**)&sin_,  g_sin);
    cudaGetSymbolAddress((void**)&kbuf,  g_kbuf);
    cudaGetSymbolAddress((void**)&sbuf,  g_sbuf);
    cudaGetSymbolAddress((void**)&feat,  g_feat);
    cudaGetSymbolAddress((void**)&hbuf,  g_hbuf);
    cudaGetSymbolAddress((void**)&awk,   g_awk);
    cudaGetSymbolAddress((void**)&aws,   g_aws);
    cudaGetSymbolAddress((void**)&awh1,  g_awh1);
    cudaGetSymbolAddress((void**)&awh2,  g_awh2);
    cudaGetSymbolAddress((void**)&biask, g_biask);
    cudaGetSymbolAddress((void**)&biass, g_biass);
    cudaGetSymbolAddress((void**)&biash, g_biash);

    cudaFuncSetAttribute(towers_kernel,
                         cudaFuncAttributeMaxDynamicSharedMemorySize, SMEM_TOWERS);
    cudaFuncSetAttribute(head_kernel<true, 1>,
                         cudaFuncAttributeMaxDynamicSharedMemorySize, SMEM_HEAD1);
    cudaFuncSetAttribute(head_kernel<false, 0>,
                         cudaFuncAttributeMaxDynamicSharedMemorySize, SMEM_HEAD2);
    cudaFuncSetAttribute(xcorr_kernel,
                         cudaFuncAttributeMaxDynamicSharedMemorySize, XC_SMEM);

    // ---- prep ----
    nchw2nhwc<<<dim3(2, 8, BATCH), 256>>>(in_kernel, kin, 49);
    nchw2nhwc<<<dim3(31, 8, BATCH), 256>>>(in_search, sin_, 961);

    permute_w<<<(294912 + 255) / 256, 256>>>(wk, gk, bk, mk, vk, awk, biask, 2304, 9, 1);
    permute_w<<<(294912 + 255) / 256, 256>>>(ws, gs, bs, ms, vs, aws, biass, 2304, 9, 1);
    permute_w<<<(32768 + 255) / 256, 256>>>(wh1, gh, bh, mh, vh, awh1, biash, 256, 1, 1);
    permute_w<<<(32768 + 255) / 256, 256>>>(wh2, nullptr, nullptr, nullptr, nullptr,
                                            awh2, nullptr, 256, 1, 0);

    // ---- towers (merged) ----
    towers_kernel<<<dim3(866, 2), 256, SMEM_TOWERS>>>(
        sin_, aws, biass, sbuf, kin, awk, biask, kbuf);

    // ---- xcorr (exact fp32 -> fp16 NHWC) ----
    xcorr_kernel<<<BATCH * 16, 256, XC_SMEM>>>(sbuf, kbuf, feat);

    // ---- heads ----
    head_kernel<true, 1><<<dim3(625, 2), 256, SMEM_HEAD1>>>(
        feat, awh1, biash, nullptr, hbuf);
    head_kernel<false, 0><<<dim3(625, 2), 256, SMEM_HEAD2>>>(
        hbuf, awh2, bh2, out, nullptr);
}

// round 7
// speedup vs baseline: 5.7477x; 1.0391x over previous
#include <cuda_runtime.h>
#include <cuda_fp16.h>
#include <cstdint>
#include <math.h>

#define BATCH 128
#define CIN   256
#define HCH   256

// ---------------- scratch ----------------
__device__ __half   g_kin [BATCH * 49 * CIN];      // NHWC fp16 kernel input
__device__ __half   g_sin [BATCH * 961 * CIN];     // NHWC fp16 search input
__device__ __half   g_kbuf[BATCH * HCH * 25];      // tower out NCHW fp16
__device__ __half   g_sbuf[BATCH * HCH * 841];
__device__ __half   g_feat[BATCH * 625 * HCH];     // xcorr out NHWC fp16
__device__ uint32_t g_awk [294912];                // permuted f16x2 weights
__device__ uint32_t g_aws [294912];
__device__ uint32_t g_awh1[32768];
__device__ uint32_t g_awh2[32768];
__device__ float    g_biask[HCH];
__device__ float    g_biass[HCH];
__device__ float    g_biash[HCH];

// ---------------- helpers ----------------
__device__ __forceinline__ uint32_t smem_u32(const void* p) {
    uint32_t a;
    asm("{ .reg .u64 t; cvta.to.shared.u64 t, %1; cvt.u32.u64 %0, t; }" : "=r"(a) : "l"(p));
    return a;
}
__device__ __forceinline__ void mma_f16(float c[4], const unsigned a[4], const unsigned b[2]) {
    asm volatile(
        "mma.sync.aligned.m16n8k16.row.col.f32.f16.f16.f32 "
        "{%0,%1,%2,%3}, {%4,%5,%6,%7}, {%8,%9}, {%0,%1,%2,%3};"
        : "+f"(c[0]), "+f"(c[1]), "+f"(c[2]), "+f"(c[3])
        : "r"(a[0]), "r"(a[1]), "r"(a[2]), "r"(a[3]), "r"(b[0]), "r"(b[1]));
}

#define CP16(dst, src) \
    asm volatile("cp.async.ca.shared.global [%0], [%1], 16;" :: "r"(dst), "l"(src) : "memory")
#define CP_COMMIT() asm volatile("cp.async.commit_group;" ::: "memory")
#define CP_WAIT0()  asm volatile("cp.async.wait_group 0;" ::: "memory")

#define LDS128(r0, r1, r2, r3, addr) \
    asm volatile("ld.shared.v4.b32 {%0,%1,%2,%3}, [%4];" \
        : "=r"(r0), "=r"(r1), "=r"(r2), "=r"(r3) : "r"(addr))
#define LDS32(r0, addr) \
    asm volatile("ld.shared.b32 %0, [%1];" : "=r"(r0) : "r"(addr))

// ---------------- prep: NCHW fp32 -> NHWC fp16 ----------------
__global__ void nchw2nhwc(const float* __restrict__ in, __half* __restrict__ out, int HW)
{
    __shared__ float tile[32][33];
    const int hw0 = blockIdx.x * 32;
    const int c0  = blockIdx.y * 32;
    const int b   = blockIdx.z;
    const int tid = threadIdx.x;

    const int hwl = tid & 31;
    const int cl  = tid >> 5;
#pragma unroll
    for (int pass = 0; pass < 4; pass++) {
        int c = cl + pass * 8;
        int hw = hw0 + hwl;
        tile[c][hwl] = (hw < HW) ? in[((size_t)b * CIN + c0 + c) * HW + hw] : 0.f;
    }
    __syncthreads();

    const int hwo = tid >> 3;
    const int cq  = (tid & 7) * 4;
    if (hw0 + hwo < HW) {
        __half2 h0 = __floats2half2_rn(tile[cq + 0][hwo], tile[cq + 1][hwo]);
        __half2 h1 = __floats2half2_rn(tile[cq + 2][hwo], tile[cq + 3][hwo]);
        __half2* dst = reinterpret_cast<__half2*>(
            out + ((size_t)b * HW + hw0 + hwo) * CIN + c0 + cq);
        dst[0] = h0;
        dst[1] = h1;
    }
}

// ---------------- prep: fold BN + permute weights (fragment order) ----------
__device__ __forceinline__ void permute_one(
    const float* __restrict__ w, const float* __restrict__ gamma,
    const float* __restrict__ beta, const float* __restrict__ mean,
    const float* __restrict__ var, uint32_t* __restrict__ awOut,
    float* __restrict__ biasOut, int K, int KK, int hasBN, int o)
{
    if (o < 256 && hasBN) {
        float inv = rsqrtf(var[o] + 1e-5f) * gamma[o];
        biasOut[o] = beta[o] - mean[o] * inv;
    }
    if (o >= 256 * K / 2) return;

    const int perMb = (K / 32) * 2048;
    int mb = o / perMb;
    int r  = o - mb * perMb;
    int gi = r >> 11;
    int r2 = r & 2047;
    int ks   = r2 >> 10;
    int mi   = (r2 >> 7) & 7;
    int lane = (r2 >> 2) & 31;
    int slot = r2 & 3;

    int row = mb * 128 + mi * 16 + (lane >> 2) + (slot & 1) * 8;
    int k0  = gi * 32 + ks * 16 + (lane & 3) * 2 + ((slot >> 1) & 1) * 8;

    float inv = hasBN ? (rsqrtf(var[row] + 1e-5f) * gamma[row]) : 1.f;

    uint32_t packed = 0;
#pragma unroll
    for (int h = 0; h < 2; h++) {
        int k = k0 + h;
        int col;
        if (KK == 9) { int uv = k >> 8; int ic = k & 255; col = ic * 9 + uv; }
        else col = k;
        float v = w[(size_t)row * K + col] * inv;
        __half hv = __float2half_rn(v);
        packed |= (uint32_t)__half_as_ushort(hv) << (h * 16);
    }
    awOut[o] = packed;
}

__global__ void permute_towers(const float* w0, const float* g0, const float* b0,
                               const float* m0, const float* v0, uint32_t* aw0, float* bias0,
                               const float* w1, const float* g1, const float* b1,
                               const float* m1, const float* v1, uint32_t* aw1, float* bias1)
{
    int o = blockIdx.x * blockDim.x + threadIdx.x;
    if (blockIdx.y == 0)
        permute_one(w0, g0, b0, m0, v0, aw0, bias0, 2304, 9, 1, o);
    else
        permute_one(w1, g1, b1, m1, v1, aw1, bias1, 2304, 9, 1, o);
}

__global__ void permute_heads(const float* w0, const float* g0, const float* b0,
                              const float* m0, const float* v0, uint32_t* aw0, float* bias0,
                              const float* w1, uint32_t* aw1)
{
    int o = blockIdx.x * blockDim.x + threadIdx.x;
    if (blockIdx.y == 0)
        permute_one(w0, g0, b0, m0, v0, aw0, bias0, 256, 1, 1, o);
    else
        permute_one(w1, nullptr, nullptr, nullptr, nullptr, aw1, nullptr, 256, 1, 0, o);
}

// ---------------------------------------------------------------------------
// Towers: fp16 m16n8k16 implicit-GEMM, NHWC in, fp16 NCHW out.
// CTA tile 128(oc) x 128(n), BK=32, 2-stage cp.async.
// ---------------------------------------------------------------------------
#define STAGE 18432
#define SMEM_PIPE (2 * STAGE)

template<int KS>
__device__ __forceinline__ void
tower_body(const __half* __restrict__ in,
           const uint32_t* __restrict__ aw,
           const float* __restrict__ bias,
           __half* __restrict__ outH,
           int Hin, int Win, int Wout, int PIX, int tileX, int mb)
{
    extern __shared__ char smem[];
    const uint32_t sb = smem_u32(smem);
    const int K = CIN * KS * KS;
    const int NITER = K >> 5;

    const int tid  = threadIdx.x;
    const int lane = tid & 31;
    const int warp = tid >> 5;
    const int wm = warp >> 2, wn = warp & 3;
    const int g = lane >> 2, c = lane & 3;
    const int m0 = mb * 128, n0 = tileX * 128;

    const int bn  = tid & 127;
    const int bkh = (tid >> 7) << 4;
    const int gn  = n0 + bn;
    const int b  = gn / PIX;
    const int p  = gn - b * PIX;
    const int py = p / Wout;
    const int px = p - py * Wout;
    const __half* inb = in + ((size_t)(b * Hin + py) * Win + px) * 256;

    const uint32_t* awBlk = aw + (size_t)mb * (K / 32) * 2048;

    auto issue = [&](int gi) {
        const uint32_t stg = sb + (uint32_t)(gi & 1) * STAGE;
        const uint32_t* asrc = awBlk + (size_t)gi * 2048 + tid * 8;
        CP16(stg + tid * 32,      asrc);
        CP16(stg + tid * 32 + 16, asrc + 4);
        int uv = gi >> 3;
        int u = uv / 3, v = uv - u * 3;
        int koff = (u * Win + v) * 256 + (gi & 7) * 32 + bkh;
        const __half* bsrc = inb + koff;
        uint32_t bd = stg + 8192u + (uint32_t)bn * 80 + bkh * 2;
        CP16(bd,      bsrc);
        CP16(bd + 16, bsrc + 8);
        CP_COMMIT();
    };

    float acc[4][4][4];
#pragma unroll
    for (int i = 0; i < 4; i++)
#pragma unroll
        for (int j = 0; j < 4; j++)
#pragma unroll
            for (int e = 0; e < 4; e++) acc[i][j][e] = 0.f;

    issue(0);

    for (int i = 0; i < NITER; i++) {
        CP_WAIT0();
        __syncthreads();
        if (i + 1 < NITER) issue(i + 1);

        const uint32_t sA = sb + (uint32_t)(i & 1) * STAGE;
        const uint32_t sB = sA + 8192u;
#pragma unroll
        for (int ks = 0; ks < 2; ks++) {
            unsigned afr[4][4], bfr[4][2];
#pragma unroll
            for (int ii = 0; ii < 4; ii++) {
                uint32_t a = sA + (uint32_t)((ks * 8 + wm * 4 + ii) << 9) + lane * 16;
                LDS128(afr[ii][0], afr[ii][1], afr[ii][2], afr[ii][3], a);
            }
#pragma unroll
            for (int j = 0; j < 4; j++) {
                uint32_t a = sB + (uint32_t)(((wn * 4 + j) * 8 + g) * 80 + ks * 32 + c * 4);
                LDS32(bfr[j][0], a);
                LDS32(bfr[j][1], a + 16);
            }
#pragma unroll
            for (int ii = 0; ii < 4; ii++)
#pragma unroll
                for (int j = 0; j < 4; j++)
                    mma_f16(acc[ii][j], afr[ii], bfr[j]);
        }
    }

    // direct fp16 NCHW scatter (bias + ReLU)
#pragma unroll
    for (int ii = 0; ii < 4; ii++) {
        int ocA = m0 + wm * 64 + ii * 16 + g;
        int ocB = ocA + 8;
        float biA = bias[ocA];
        float biB = bias[ocB];
#pragma unroll
        for (int j = 0; j < 4; j++) {
            int nb = n0 + wn * 32 + j * 8 + c * 2;
#pragma unroll
            for (int e = 0; e < 4; e++) {
                int nn = nb + (e & 1);
                int oc = (e < 2) ? ocA : ocB;
                float v = fmaxf(acc[ii][j][e] + ((e < 2) ? biA : biB), 0.f);
                int bb = nn / PIX;
                int pp = nn - bb * PIX;
                outH[((size_t)bb * HCH + oc) * PIX + pp] = __float2half_rn(v);
            }
        }
    }
}

__global__ void __launch_bounds__(256)
towers_kernel(const __half* __restrict__ sIn, const uint32_t* __restrict__ sAw,
              const float* __restrict__ sBias, __half* __restrict__ sOut,
              const __half* __restrict__ kIn, const uint32_t* __restrict__ kAw,
              const float* __restrict__ kBias, __half* __restrict__ kOut)
{
    if (blockIdx.x < 841)
        tower_body<3>(sIn, sAw, sBias, sOut, 31, 31, 29, 841, blockIdx.x, blockIdx.y);
    else
        tower_body<3>(kIn, kAw, kBias, kOut, 7, 7, 5, 25, blockIdx.x - 841, blockIdx.y);
}

// ---------------------------------------------------------------------------
// Fused head: h = relu(bn(feat*w1)) kept in smem; out = h*w2 + b2.
// CTA = 128 flattened pixels, full 256 channels (2 m-halves per stage).
// smem: [0, 36864) pipe; [36864, +67584) h (128 rows x 528 B).
// ---------------------------------------------------------------------------
#define HF_H    36864
#define HF_SMEM (36864 + 67584)

__global__ void __launch_bounds__(256)
head_fused(const __half* __restrict__ feat,
           const uint32_t* __restrict__ aw1, const float* __restrict__ bias1,
           const uint32_t* __restrict__ aw2, const float* __restrict__ bias2,
           float* __restrict__ out)
{
    extern __shared__ char smem[];
    const uint32_t sb = smem_u32(smem);
    __half* hsm = reinterpret_cast<__half*>(smem + HF_H);

    const int tid  = threadIdx.x;
    const int lane = tid & 31;
    const int warp = tid >> 5;
    const int wm = warp >> 2, wn = warp & 3;
    const int g = lane >> 2, c = lane & 3;
    const int n0 = blockIdx.x * 128;

    const int bn  = tid & 127;
    const int bkh = (tid >> 7) << 4;
    const __half* inb = feat + (size_t)(n0 + bn) * 256;

    float acc[4][4][4];

    // ================= stage 1: h = relu(bn(feat * w1)) =================
#pragma unroll 1
    for (int mb = 0; mb < 2; mb++) {
        const uint32_t* awBlk = aw1 + (size_t)mb * 8 * 2048;
#pragma unroll
        for (int i = 0; i < 4; i++)
#pragma unroll
            for (int j = 0; j < 4; j++)
#pragma unroll
                for (int e = 0; e < 4; e++) acc[i][j][e] = 0.f;

        auto issue1 = [&](int gi) {
            const uint32_t stg = sb + (uint32_t)(gi & 1) * STAGE;
            const uint32_t* asrc = awBlk + (size_t)gi * 2048 + tid * 8;
            CP16(stg + tid * 32,      asrc);
            CP16(stg + tid * 32 + 16, asrc + 4);
            const __half* bsrc = inb + gi * 32 + bkh;
            uint32_t bd = stg + 8192u + (uint32_t)bn * 80 + bkh * 2;
            CP16(bd,      bsrc);
            CP16(bd + 16, bsrc + 8);
            CP_COMMIT();
        };

        issue1(0);
        for (int i = 0; i < 8; i++) {
            CP_WAIT0();
            __syncthreads();
            if (i < 7) issue1(i + 1);
            const uint32_t sA = sb + (uint32_t)(i & 1) * STAGE;
            const uint32_t sB = sA + 8192u;
#pragma unroll
            for (int ks = 0; ks < 2; ks++) {
                unsigned afr[4][4], bfr[4][2];
#pragma unroll
                for (int ii = 0; ii < 4; ii++) {
                    uint32_t a = sA + (uint32_t)((ks * 8 + wm * 4 + ii) << 9) + lane * 16;
                    LDS128(afr[ii][0], afr[ii][1], afr[ii][2], afr[ii][3], a);
                }
#pragma unroll
                for (int j = 0; j < 4; j++) {
                    uint32_t a = sB + (uint32_t)(((wn * 4 + j) * 8 + g) * 80 + ks * 32 + c * 4);
                    LDS32(bfr[j][0], a);
                    LDS32(bfr[j][1], a + 16);
                }
#pragma unroll
                for (int ii = 0; ii < 4; ii++)
#pragma unroll
                    for (int j = 0; j < 4; j++)
                        mma_f16(acc[ii][j], afr[ii], bfr[j]);
            }
        }

        // write h tile to smem (bias + relu, fp16)
#pragma unroll
        for (int ii = 0; ii < 4; ii++) {
            int oclA = mb * 128 + wm * 64 + ii * 16 + g;
            float biA = bias1[oclA];
            float biB = bias1[oclA + 8];
#pragma unroll
            for (int j = 0; j < 4; j++) {
                int nl = wn * 32 + j * 8 + c * 2;
#pragma unroll
                for (int e = 0; e < 4; e++) {
                    int n = nl + (e & 1);
                    int ocl = oclA + ((e < 2) ? 0 : 8);
                    float v = fmaxf(acc[ii][j][e] + ((e < 2) ? biA : biB), 0.f);
                    hsm[n * 264 + ocl] = __float2half_rn(v);
                }
            }
        }
    }
    __syncthreads();   // h fully visible

    // ================= stage 2: out = h * w2 + b2 =================
#pragma unroll 1
    for (int mb2 = 0; mb2 < 2; mb2++) {
        const uint32_t* awBlk = aw2 + (size_t)mb2 * 8 * 2048;
#pragma unroll
        for (int i = 0; i < 4; i++)
#pragma unroll
            for (int j = 0; j < 4; j++)
#pragma unroll
                for (int e = 0; e < 4; e++) acc[i][j][e] = 0.f;

        auto issue2 = [&](int gi) {
            const uint32_t stg = sb + (uint32_t)(gi & 1) * STAGE;
            const uint32_t* asrc = awBlk + (size_t)gi * 2048 + tid * 8;
            CP16(stg + tid * 32,      asrc);
            CP16(stg + tid * 32 + 16, asrc + 4);
            CP_COMMIT();
        };

        issue2(0);
        for (int i = 0; i < 8; i++) {
            CP_WAIT0();
            __syncthreads();
            if (i < 7) issue2(i + 1);
            const uint32_t sA = sb + (uint32_t)(i & 1) * STAGE;
            const uint32_t hB = sb + HF_H;
#pragma unroll
            for (int ks = 0; ks < 2; ks++) {
                unsigned afr[4][4], bfr[4][2];
#pragma unroll
                for (int ii = 0; ii < 4; ii++) {
                    uint32_t a = sA + (uint32_t)((ks * 8 + wm * 4 + ii) << 9) + lane * 16;
                    LDS128(afr[ii][0], afr[ii][1], afr[ii][2], afr[ii][3], a);
                }
#pragma unroll
                for (int j = 0; j < 4; j++) {
                    uint32_t a = hB + (uint32_t)(((wn * 4 + j) * 8 + g) * 528
                                                 + i * 64 + ks * 32 + c * 4);
                    LDS32(bfr[j][0], a);
                    LDS32(bfr[j][1], a + 16);
                }
#pragma unroll
                for (int ii = 0; ii < 4; ii++)
#pragma unroll
                    for (int j = 0; j < 4; j++)
                        mma_f16(acc[ii][j], afr[ii], bfr[j]);
            }
        }

        // epilogue: fp32 NCHW scatter with bias2 (no relu)
#pragma unroll
        for (int ii = 0; ii < 4; ii++) {
            int ocA = mb2 * 128 + wm * 64 + ii * 16 + g;
            int ocB = ocA + 8;
            float biA = bias2[ocA];
            float biB = bias2[ocB];
#pragma unroll
            for (int j = 0; j < 4; j++) {
                int nb = n0 + wn * 32 + j * 8 + c * 2;
#pragma unroll
                for (int e = 0; e < 4; e++) {
                    int nn = nb + (e & 1);
                    int oc = (e < 2) ? ocA : ocB;
                    float v = acc[ii][j][e] + ((e < 2) ? biA : biB);
                    int bb = nn / 625;
                    int pp = nn - bb * 625;
                    out[((size_t)bb * HCH + oc) * 625 + pp] = v;
                }
            }
        }
    }
}

// ---------------------------------------------------------------------------
// Depthwise xcorr: fp16 NCHW in, fp32 accum, fp16 NHWC out.
// ---------------------------------------------------------------------------
#define XC_SMEM (16 * 841 * 4 + 16 * 25 * 4)

__global__ void xcorr_kernel(const __half* __restrict__ s,
                             const __half* __restrict__ k,
                             __half* __restrict__ feat)
{
    extern __shared__ float xs[];
    float* ss = xs;
    float* kk = xs + 16 * 841;
    const int cg = blockIdx.x & 15;
    const int b  = blockIdx.x >> 4;
    const int tid = threadIdx.x;

    const __half* sp = s + ((size_t)b * 256 + cg * 16) * 841;
    const __half* kp = k + ((size_t)b * 256 + cg * 16) * 25;
    for (int i = tid; i < 16 * 841; i += 256) ss[i] = __half2float(sp[i]);
    for (int i = tid; i < 16 * 25; i += 256) kk[i] = __half2float(kp[i]);
    __syncthreads();

    const int c  = tid & 15;
    const int p0 = tid >> 4;
    const float* sc = ss + c * 841;
    const float* kc = kk + c * 25;
    for (int p = p0; p < 625; p += 16) {
        int y = p / 25, x = p - (p / 25) * 25;
        float acc = 0.f;
#pragma unroll
        for (int u = 0; u < 5; u++)
#pragma unroll
            for (int v = 0; v < 5; v++)
                acc += sc[(y + u) * 29 + x + v] * kc[u * 5 + v];
        feat[((size_t)b * 625 + p) * 256 + cg * 16 + c] = __float2half_rn(acc);
    }
}

// ---------------------------------------------------------------------------
extern "C" void kernel_launch(void* const* d_in, const int* in_sizes, int n_in,
                              void* d_out, int out_size)
{
    (void)in_sizes; (void)n_in; (void)out_size;
    const float* in_kernel = (const float*)d_in[0];
    const float* in_search = (const float*)d_in[1];
    const float* wk = (const float*)d_in[2];
    const float* gk = (const float*)d_in[3];
    const float* bk = (const float*)d_in[4];
    const float* mk = (const float*)d_in[5];
    const float* vk = (const float*)d_in[6];
    const float* ws = (const float*)d_in[7];
    const float* gs = (const float*)d_in[8];
    const float* bs = (const float*)d_in[9];
    const float* ms = (const float*)d_in[10];
    const float* vs = (const float*)d_in[11];
    const float* wh1 = (const float*)d_in[12];
    const float* gh  = (const float*)d_in[13];
    const float* bh  = (const float*)d_in[14];
    const float* mh  = (const float*)d_in[15];
    const float* vh  = (const float*)d_in[16];
    const float* wh2 = (const float*)d_in[17];
    const float* bh2 = (const float*)d_in[18];
    float* out = (float*)d_out;

    __half *kin, *sin_, *kbuf, *sbuf, *feat;
    float *biask, *biass, *biash;
    uint32_t *awk, *aws, *awh1, *awh2;
    cudaGetSymbolAddress((void**)&kin,   g_kin);
    cudaGetSymbolAddress((void**)&sin_,  g_sin);
    cudaGetSymbolAddress((void**)&kbuf,  g_kbuf);
    cudaGetSymbolAddress((void**)&sbuf,  g_sbuf);
    cudaGetSymbolAddress((void**)&feat,  g_feat);
    cudaGetSymbolAddress((void**)&awk,   g_awk);
    cudaGetSymbolAddress((void**)&aws,   g_aws);
    cudaGetSymbolAddress((void**)&awh1,  g_awh1);
    cudaGetSymbolAddress((void**)&awh2,  g_awh2);
    cudaGetSymbolAddress((void**)&biask, g_biask);
    cudaGetSymbolAddress((void**)&biass, g_biass);
    cudaGetSymbolAddress((void**)&biash, g_biash);

    cudaFuncSetAttribute(towers_kernel,
                         cudaFuncAttributeMaxDynamicSharedMemorySize, SMEM_PIPE);
    cudaFuncSetAttribute(head_fused,
                         cudaFuncAttributeMaxDynamicSharedMemorySize, HF_SMEM);
    cudaFuncSetAttribute(xcorr_kernel,
                         cudaFuncAttributeMaxDynamicSharedMemorySize, XC_SMEM);

    // ---- prep ----
    nchw2nhwc<<<dim3(2, 8, BATCH), 256>>>(in_kernel, kin, 49);
    nchw2nhwc<<<dim3(31, 8, BATCH), 256>>>(in_search, sin_, 961);

    permute_towers<<<dim3(1152, 2), 256>>>(wk, gk, bk, mk, vk, awk, biask,
                                           ws, gs, bs, ms, vs, aws, biass);
    permute_heads<<<dim3(128, 2), 256>>>(wh1, gh, bh, mh, vh, awh1, biash,
                                         wh2, awh2);

    // ---- towers (merged, fp16 NCHW out) ----
    towers_kernel<<<dim3(866, 2), 256, SMEM_PIPE>>>(
        sin_, aws, biass, sbuf, kin, awk, biask, kbuf);

    // ---- xcorr (fp32 accum -> fp16 NHWC) ----
    xcorr_kernel<<<BATCH * 16, 256, XC_SMEM>>>(sbuf, kbuf, feat);

    // ---- fused head ----
    head_fused<<<625, 256, HF_SMEM>>>(feat, awh1, biash, awh2, bh2, out);
}